// round 14
// baseline (speedup 1.0000x reference)
#include <cuda_runtime.h>
#include <math.h>

#define NN 2048
#define EE 65536
#define HID 64
#define HEADS 4
#define HD 16
#define KC 25
#define PRED_DIM 7

typedef unsigned long long ull;

__device__ float g_h0[NN*HID];
__device__ float g_h1[NN*HID];
__device__ float g_h2[NN*HID];
__device__ float g_bufA[NN*HID];
__device__ float g_bufB[NN*HID];
__device__ float g_tmp[NN*HID];
__device__ float g_loop[NN*6];
__device__ __align__(16) float g_sums[NN*8];
__device__ int   g_idx[KC];
__device__ float g_feats[KC*HID];
__device__ int   g_cnt[NN];
__device__ int   g_rowptr[NN+1];
__device__ int   g_eids[EE];

// ---- packed f32x2 ----
__device__ __forceinline__ ull px2_add(ull a, ull b){
    ull r; asm("add.rn.f32x2 %0,%1,%2;" : "=l"(r) : "l"(a), "l"(b)); return r;
}
__device__ __forceinline__ ull px2_fma(ull a, ull b, ull c){
    ull r; asm("fma.rn.f32x2 %0,%1,%2,%3;" : "=l"(r) : "l"(a), "l"(b), "l"(c)); return r;
}
__device__ __forceinline__ ull px2_dup(float x){
    ull r; asm("mov.b64 %0,{%1,%1};" : "=l"(r) : "f"(x)); return r;
}

#define RED4(ptr, a,b,c,d) \
    asm volatile("red.global.add.v4.f32 [%0], {%1,%2,%3,%4};" \
                 :: "l"(ptr), "f"(a), "f"(b), "f"(c), "f"(d) : "memory")

// ---- JAX threefry2x32 ----
__device__ __forceinline__ void tf2x32(unsigned k0, unsigned k1, unsigned x0, unsigned x1,
                                       unsigned& o0, unsigned& o1){
    unsigned ks2 = k0 ^ k1 ^ 0x1BD11BDAu;
    x0 += k0; x1 += k1;
#define TFR(r) { x0 += x1; x1 = (x1 << (r)) | (x1 >> (32 - (r))); x1 ^= x0; }
    TFR(13) TFR(15) TFR(26) TFR(6)
    x0 += k1; x1 += ks2 + 1u;
    TFR(17) TFR(29) TFR(16) TFR(24)
    x0 += ks2; x1 += k0 + 2u;
    TFR(13) TFR(15) TFR(26) TFR(6)
    x0 += k0; x1 += k1 + 3u;
    TFR(17) TFR(29) TFR(16) TFR(24)
    x0 += k1; x1 += ks2 + 4u;
    TFR(13) TFR(15) TFR(26) TFR(6)
    x0 += ks2; x1 += k0 + 5u;
#undef TFR
    o0 = x0; o1 = x1;
}
__device__ __forceinline__ unsigned tf_bits32(unsigned k0, unsigned k1, unsigned i){
    unsigned o0, o1;
    tf2x32(k0, k1, 0u, i, o0, o1);
    return o0 ^ o1;
}
__device__ __forceinline__ float gumbel_from_bits(unsigned b){
    const float TINY = 1.17549435e-38f;
    float f = __uint_as_float((b >> 9) | 0x3f800000u) - 1.0f;
    float u = fmaxf(TINY, f*(1.0f - TINY) + TINY);
    return -logf(-logf(u));
}

// ---- encoder L1 ----
__global__ void enc1_kernel(const float* __restrict__ x, const float* __restrict__ pos,
                            const int* __restrict__ ntype, const float* __restrict__ temb,
                            const float* __restrict__ w1, const float* __restrict__ b1,
                            float* __restrict__ out){
    __shared__ float ws[15*HID];
    for (int i = threadIdx.x; i < 15*HID; i += blockDim.x) ws[i] = w1[i];
    __syncthreads();
    int idx = blockIdx.x*blockDim.x + threadIdx.x;
    if (idx >= NN*HID) return;
    int n = idx >> 6, c = idx & 63;
    float nf[15];
    nf[0]=x[n*4+0]; nf[1]=x[n*4+1]; nf[2]=x[n*4+2]; nf[3]=x[n*4+3];
    nf[4]=pos[n*3+0]; nf[5]=pos[n*3+1]; nf[6]=pos[n*3+2];
    int t = ntype[n];
    #pragma unroll
    for (int d=0; d<8; d++) nf[7+d] = temb[t*8+d];
    float acc = b1[c];
    #pragma unroll
    for (int d=0; d<15; d++) acc += nf[d]*ws[d*HID+c];
    out[idx] = fmaxf(acc, 0.f);
}

// ---- single [N,64]x[64,64] ----
__global__ void gemm64_kernel(const float* __restrict__ in, const float* __restrict__ w,
                              const float* __restrict__ b, float* __restrict__ out, int act){
    __shared__ float ws[HID*HID];
    __shared__ float ins[4][HID];
    int tid = threadIdx.x;
    for (int i = tid; i < HID*HID; i += 256) ws[i] = w[i];
    int r = tid >> 6, c = tid & 63;
    int row = blockIdx.x*4 + r;
    ins[r][c] = in[row*HID + c];
    __syncthreads();
    float acc = b ? b[c] : 0.f;
    #pragma unroll
    for (int k=0;k<HID;k++) acc += ins[r][k]*ws[k*HID+c];
    if (act) acc = fmaxf(acc, 0.f);
    out[row*HID+c] = acc;
}

// ---- dual [N,64]x[64,64] ----
__global__ void gemm64_dual_kernel(const float* __restrict__ in,
                                   const float* __restrict__ wA, const float* __restrict__ bA,
                                   const float* __restrict__ wB, const float* __restrict__ bB,
                                   float* __restrict__ oA, float* __restrict__ oB){
    __shared__ float wsA[HID*HID];
    __shared__ float wsB[HID*HID];
    __shared__ float ins[4][HID];
    int tid = threadIdx.x;
    for (int i = tid; i < HID*HID; i += 256){ wsA[i] = wA[i]; wsB[i] = wB[i]; }
    int r = tid >> 6, c = tid & 63;
    int row = blockIdx.x*4 + r;
    ins[r][c] = in[row*HID + c];
    __syncthreads();
    float aA = bA ? bA[c] : 0.f;
    float aB = bB ? bB[c] : 0.f;
    #pragma unroll
    for (int k=0;k<HID;k++){
        float v = ins[r][k];
        aA += v*wsA[k*HID+c];
        aB += v*wsB[k*HID+c];
    }
    oA[row*HID+c] = aA;
    oB[row*HID+c] = aB;
}

// ---- self-loop attrs (red.v4 path) ----
__global__ void loop_zero_kernel(){
    int i = blockIdx.x*blockDim.x+threadIdx.x;
    if (i < NN*8) g_sums[i]=0.f;
    if (i < NN) g_cnt[i]=0;               // CSR histogram reset, fused here
}
__global__ void loop_accum_kernel(const int* __restrict__ ei, const float* __restrict__ ea){
    int e = blockIdx.x*blockDim.x+threadIdx.x;
    if (e >= EE) return;
    int dst = ei[EE + e];
    atomicAdd(&g_cnt[dst], 1);            // CSR histogram, fused here
    float2 e01 = *(const float2*)(ea + e*6);
    float2 e23 = *(const float2*)(ea + e*6 + 2);
    float2 e45 = *(const float2*)(ea + e*6 + 4);
    float* p = &g_sums[dst*8];
    RED4(p,   e01.x, e01.y, e23.x, e23.y);
    RED4(p+4, e45.x, e45.y, 1.0f, 0.0f);
}
__global__ void loop_fin_kernel(){
    int i = blockIdx.x*blockDim.x+threadIdx.x;
    if (i >= NN*6) return;
    int n = i/6, d = i%6;
    g_loop[i] = g_sums[n*8+d] / fmaxf(g_sums[n*8+6], 1.f);
}

// ---- CSR scan: 1 block, 1024 threads, inclusive scan of g_cnt[2048] ----
__global__ void __launch_bounds__(1024) csr_scan_kernel(){
    __shared__ int sm[NN];
    int tid = threadIdx.x;
    sm[tid]      = g_cnt[tid];
    sm[tid+1024] = g_cnt[tid+1024];
    __syncthreads();
    for (int off=1; off<NN; off<<=1){
        int a = (tid        >= off) ? sm[tid-off]      : 0;
        int b = (tid+1024   >= off) ? sm[tid+1024-off] : 0;
        __syncthreads();
        sm[tid]      += a;
        sm[tid+1024] += b;
        __syncthreads();
    }
    if (tid == 0) g_rowptr[0] = 0;
    g_rowptr[tid+1]    = sm[tid];
    g_rowptr[tid+1025] = sm[tid+1024];
    g_cnt[tid] = 0;
    g_cnt[tid+1024] = 0;
}

__global__ void csr_scatter_kernel(const int* __restrict__ ei){
    int e = blockIdx.x*blockDim.x+threadIdx.x;
    if (e >= EE) return;
    int dst = ei[EE + e];
    int r = atomicAdd(&g_cnt[dst], 1);
    g_eids[g_rowptr[dst] + r] = e;
}

// ---- fused GATv2 layer: block=dst, warp=head, lane=edge; online softmax ----
__global__ void __launch_bounds__(128) gat_fused_kernel(
        const int* __restrict__ ei, const float* __restrict__ ea,
        const float* __restrict__ we, const float* __restrict__ att,
        const float* __restrict__ bias,
        const float* __restrict__ xl, const float* __restrict__ xr,
        float* __restrict__ hout, int act){
    __shared__ float wes[6*HID];
    __shared__ float atts[HID];
    __shared__ float xrs[HID];
    __shared__ float loop6[6];
    int dst = blockIdx.x;
    int tid = threadIdx.x;
    int h = tid >> 5, lane = tid & 31;
    for (int i=tid;i<6*HID;i+=128) wes[i]=we[i];
    if (tid < HID){ atts[tid]=att[tid]; xrs[tid]=xr[dst*HID+tid]; }
    if (tid < 6) loop6[tid] = g_loop[dst*6+tid];
    __syncthreads();
    int beg = g_rowptr[dst], nit = g_rowptr[dst+1] - beg + 1;  // + self loop
    int base = h*HD;
    float xrr[HD], atr[HD];
    #pragma unroll
    for (int k=0;k<HD;k++){ xrr[k]=xrs[base+k]; atr[k]=atts[base+k]; }

    float m = -3.4e38f, s = 0.f, acc[HD];
    #pragma unroll
    for (int k=0;k<HD;k++) acc[k]=0.f;

    for (int it = lane; it < nit; it += 32){
        int src; float eav[6];
        if (it < nit-1){
            int e = g_eids[beg+it];
            src = ei[e];
            float2 a01 = *(const float2*)(ea + e*6);
            float2 a23 = *(const float2*)(ea + e*6 + 2);
            float2 a45 = *(const float2*)(ea + e*6 + 4);
            eav[0]=a01.x; eav[1]=a01.y; eav[2]=a23.x; eav[3]=a23.y; eav[4]=a45.x; eav[5]=a45.y;
        } else {
            src = dst;
            #pragma unroll
            for (int d=0;d<6;d++) eav[d]=loop6[d];
        }
        const float4* xl4 = (const float4*)(xl + src*HID + base);
        float vv[HD];
        #pragma unroll
        for (int q=0;q<4;q++){
            float4 L = xl4[q];
            vv[q*4+0]=L.x; vv[q*4+1]=L.y; vv[q*4+2]=L.z; vv[q*4+3]=L.w;
        }
        float lo = 0.f;
        #pragma unroll
        for (int k=0;k<HD;k++){
            float v = vv[k] + xrr[k];
            #pragma unroll
            for (int d=0;d<6;d++) v += eav[d]*wes[d*HID+base+k];
            v = (v > 0.f) ? v : 0.2f*v;
            lo += v*atr[k];
        }
        // online softmax update
        if (lo > m){
            float sc = expf(m - lo);
            s *= sc;
            #pragma unroll
            for (int k=0;k<HD;k++) acc[k] *= sc;
            m = lo;
            s += 1.0f;
            #pragma unroll
            for (int k=0;k<HD;k++) acc[k] += vv[k];
        } else {
            float ex = expf(lo - m);
            s += ex;
            #pragma unroll
            for (int k=0;k<HD;k++) acc[k] += vv[k]*ex;
        }
    }
    // merge across 32 lanes
    #pragma unroll
    for (int o=16;o>0;o>>=1){
        float mo = __shfl_down_sync(0xffffffffu, m, o);
        float so = __shfl_down_sync(0xffffffffu, s, o);
        float mx = fmaxf(m, mo);
        float sa = expf(m - mx), sb = expf(mo - mx);
        float ns = s*sa + so*sb;
        #pragma unroll
        for (int k=0;k<HD;k++){
            float ao = __shfl_down_sync(0xffffffffu, acc[k], o);
            acc[k] = acc[k]*sa + ao*sb;
        }
        m = mx; s = ns;
    }
    if (lane == 0){
        #pragma unroll
        for (int k=0;k<HD;k++){
            float v = acc[k]/s + bias[base+k];
            if (act) v = fmaxf(v, 0.f);
            hout[dst*HID+base+k] = v;
        }
    }
}

// ---- association matrix: transposed smem + packed f32x2 ----
__global__ void __launch_bounds__(256) assoc_kernel(
        const float* __restrict__ si, const float* __restrict__ sj,
        const float* __restrict__ w2, const float* __restrict__ b2,
        float* __restrict__ A){
    __shared__ __align__(16) float sis[64][68];
    __shared__ __align__(16) float sjs[64][68];
    __shared__ float w2h[64];
    int tid = threadIdx.x;
    int bi = blockIdx.y*64, bj = blockIdx.x*64;
    for (int i=tid;i<64*64;i+=256){
        int r = i >> 6, c = i & 63;
        sis[c][r] = si[(bi+r)*HID + c];
        sjs[c][r] = sj[(bj+r)*HID + c];
    }
    if (tid < 64) w2h[tid] = 0.5f*w2[tid];
    __syncthreads();
    int tx = tid & 31, ty = tid >> 5;
    int ib = 8*ty, jb = 2*tx;
    const ull MASK = 0x7FFFFFFF7FFFFFFFULL;
    ull acc[4][2];
    #pragma unroll
    for (int p=0;p<4;p++){ acc[p][0]=0ULL; acc[p][1]=0ULL; }
    #pragma unroll 8
    for (int c=0;c<64;c++){
        double2 A01 = *(const double2*)&sis[c][ib];
        double2 A23 = *(const double2*)&sis[c][ib+4];
        ull ap[4] = { __double_as_longlong(A01.x), __double_as_longlong(A01.y),
                      __double_as_longlong(A23.x), __double_as_longlong(A23.y) };
        ull pv0 = px2_dup(sjs[c][jb]);
        ull pv1 = px2_dup(sjs[c][jb+1]);
        ull pw  = px2_dup(w2h[c]);
        #pragma unroll
        for (int p=0;p<4;p++){
            ull t0 = px2_add(ap[p], pv0);
            t0 = px2_add(t0, t0 & MASK);
            acc[p][0] = px2_fma(t0, pw, acc[p][0]);
            ull t1 = px2_add(ap[p], pv1);
            t1 = px2_add(t1, t1 & MASK);
            acc[p][1] = px2_fma(t1, pw, acc[p][1]);
        }
    }
    float b2v = b2[0];
    #pragma unroll
    for (int p=0;p<4;p++){
        float o00 = __uint_as_float((unsigned)(acc[p][0]));
        float o01 = __uint_as_float((unsigned)(acc[p][0]>>32));
        float o10 = __uint_as_float((unsigned)(acc[p][1]));
        float o11 = __uint_as_float((unsigned)(acc[p][1]>>32));
        int i0 = bi + ib + 2*p;
        size_t r0o = (size_t)i0*NN + bj + jb;
        size_t r1o = (size_t)(i0+1)*NN + bj + jb;
        A[r0o]   = 1.f/(1.f+expf(-(o00+b2v)));
        A[r0o+1] = 1.f/(1.f+expf(-(o10+b2v)));
        A[r1o]   = 1.f/(1.f+expf(-(o01+b2v)));
        A[r1o+1] = 1.f/(1.f+expf(-(o11+b2v)));
    }
}

// ---- soft clustering (VERBATIM; do not touch) ----
__global__ void __launch_bounds__(1024) cluster_kernel(const float* __restrict__ A){
    __shared__ float s_mind[NN];
    __shared__ float s_wv[32];
    __shared__ int   s_wi[32];
    __shared__ unsigned s_k0[KC-1], s_k1[KC-1];
    __shared__ int s_nxt;
    __shared__ float s_inv;
    __shared__ unsigned s_kq0, s_kq1;
    int tid = threadIdx.x;
    int lane = tid & 31, wid = tid >> 5;

    if (tid == 0){
        unsigned kf0,kf1, kq0,kq1;
        tf2x32(0u,42u, 0u,0u, kf0,kf1);
        tf2x32(0u,42u, 0u,1u, kq0,kq1);
        s_kq0 = kq0; s_kq1 = kq1;
        unsigned s2_0, s2_1;
        tf2x32(kf0, kf1, 0u, 1u, s2_0, s2_1);
        unsigned lower = tf_bits32(s2_0, s2_1, 0u);
        int first = (int)(lower % (unsigned)NN);
        s_nxt = first;
        g_idx[0] = first;
    }
    __syncthreads();
    if (tid < KC-1){
        unsigned o0,o1;
        tf2x32(s_kq0, s_kq1, 0u, (unsigned)tid, o0, o1);
        s_k0[tid]=o0; s_k1[tid]=o1;
    }
    __syncthreads();
    {
        int first = s_nxt;
        s_mind[tid]      = 1.0f - A[(size_t)first*NN + tid];
        s_mind[tid+1024] = 1.0f - A[(size_t)first*NN + tid + 1024];
    }
    __syncthreads();

    for (int step=0; step<KC-1; step++){
        float s = s_mind[tid] + s_mind[tid+1024];
        #pragma unroll
        for (int o=16;o>0;o>>=1) s += __shfl_down_sync(0xffffffffu, s, o);
        if (lane==0) s_wv[wid]=s;
        __syncthreads();
        if (wid==0){
            float t = s_wv[lane];
            #pragma unroll
            for (int o=16;o>0;o>>=1) t += __shfl_down_sync(0xffffffffu, t, o);
            if (lane==0) s_inv = 1.0f/(t + 1e-8f);
        }
        __syncthreads();
        float inv = s_inv;
        unsigned b0 = tf_bits32(s_k0[step], s_k1[step], (unsigned)tid);
        unsigned b1 = tf_bits32(s_k0[step], s_k1[step], (unsigned)(tid+1024));
        float sc0 = logf(fmaxf(s_mind[tid]*inv,      1e-30f)) + gumbel_from_bits(b0);
        float sc1 = logf(fmaxf(s_mind[tid+1024]*inv, 1e-30f)) + gumbel_from_bits(b1);
        float bv; int bi;
        if (sc0 >= sc1){ bv = sc0; bi = tid; } else { bv = sc1; bi = tid + 1024; }
        #pragma unroll
        for (int o=16;o>0;o>>=1){
            float ov = __shfl_down_sync(0xffffffffu, bv, o);
            int   oi = __shfl_down_sync(0xffffffffu, bi, o);
            if (ov > bv || (ov == bv && oi < bi)){ bv = ov; bi = oi; }
        }
        if (lane==0){ s_wv[wid]=bv; s_wi[wid]=bi; }
        __syncthreads();
        if (wid==0){
            float v = s_wv[lane]; int ix = s_wi[lane];
            #pragma unroll
            for (int o=16;o>0;o>>=1){
                float ov = __shfl_down_sync(0xffffffffu, v, o);
                int   oi = __shfl_down_sync(0xffffffffu, ix, o);
                if (ov > v || (ov == v && oi < ix)){ v = ov; ix = oi; }
            }
            if (lane==0){ s_nxt = ix; g_idx[step+1] = ix; }
        }
        __syncthreads();
        int nxt = s_nxt;
        s_mind[tid]      = fminf(s_mind[tid],      1.0f - A[(size_t)nxt*NN + tid]);
        s_mind[tid+1024] = fminf(s_mind[tid+1024], 1.0f - A[(size_t)nxt*NN + tid + 1024]);
        __syncthreads();
    }
}

// ---- assign ----
__global__ void assign_kernel(const float* __restrict__ A, float* __restrict__ assign){
    __shared__ int idxs[KC];
    if (threadIdx.x < KC) idxs[threadIdx.x] = g_idx[threadIdx.x];
    __syncthreads();
    int n = blockIdx.x*blockDim.x + threadIdx.x;
    if (n >= NN) return;
    float v[KC];
    float mx = -3.4e38f;
    #pragma unroll
    for (int k=0;k<KC;k++){
        v[k] = A[(size_t)n*NN + idxs[k]] * 10.0f;
        mx = fmaxf(mx, v[k]);
    }
    float sum = 0.f;
    #pragma unroll
    for (int k=0;k<KC;k++){ v[k] = expf(v[k]-mx); sum += v[k]; }
    float invs = 1.0f/sum;
    #pragma unroll
    for (int k=0;k<KC;k++) assign[n*KC+k] = v[k]*invs;
}

// ---- feats ----
__global__ void feats_kernel(const float* __restrict__ assign, const float* __restrict__ h){
    int k = blockIdx.x;
    int tid = threadIdx.x;
    int c = tid & 63, g = tid >> 6;
    __shared__ float a_s[256];
    __shared__ float part[4][HID];
    float acc = 0.f;
    for (int n0=0; n0<NN; n0+=256){
        __syncthreads();
        a_s[tid] = assign[(n0+tid)*KC + k];
        __syncthreads();
        for (int nn=g; nn<256; nn+=4)
            acc += a_s[nn]*h[(size_t)(n0+nn)*HID + c];
    }
    part[g][c] = acc;
    __syncthreads();
    if (g == 0)
        g_feats[k*HID+c] = part[0][c]+part[1][c]+part[2][c]+part[3][c];
}

// ---- preds ----
__global__ void preds_kernel(const float* __restrict__ w1, const float* __restrict__ b1,
                             const float* __restrict__ w2, const float* __restrict__ b2,
                             float* __restrict__ preds){
    __shared__ float hid[HID];
    int k = blockIdx.x, c = threadIdx.x;
    float acc = b1[c];
    #pragma unroll
    for (int d=0;d<HID;d++) acc += g_feats[k*HID+d]*w1[d*HID+c];
    hid[c] = fmaxf(acc, 0.f);
    __syncthreads();
    if (c < PRED_DIM){
        float p = b2[c];
        #pragma unroll
        for (int d=0;d<HID;d++) p += hid[d]*w2[d*PRED_DIM+c];
        preds[k*PRED_DIM+c] = p;
    }
}

extern "C" void kernel_launch(void* const* d_in, const int* in_sizes, int n_in,
                              void* d_out, int out_size) {
    const float* x        = (const float*)d_in[0];
    const float* pos      = (const float*)d_in[1];
    const int*   ntype    = (const int*)d_in[2];
    const int*   ei       = (const int*)d_in[3];
    const float* ea       = (const float*)d_in[4];
    const float* temb     = (const float*)d_in[5];
    const float* enc_w1   = (const float*)d_in[6];
    const float* enc_b1   = (const float*)d_in[7];
    const float* enc_w2   = (const float*)d_in[8];
    const float* enc_b2   = (const float*)d_in[9];
    const float* g1_wl  = (const float*)d_in[10];
    const float* g1_bl  = (const float*)d_in[11];
    const float* g1_wr  = (const float*)d_in[12];
    const float* g1_br  = (const float*)d_in[13];
    const float* g1_we  = (const float*)d_in[14];
    const float* g1_att = (const float*)d_in[15];
    const float* g1_bias= (const float*)d_in[16];
    const float* g2_wl  = (const float*)d_in[17];
    const float* g2_bl  = (const float*)d_in[18];
    const float* g2_wr  = (const float*)d_in[19];
    const float* g2_br  = (const float*)d_in[20];
    const float* g2_we  = (const float*)d_in[21];
    const float* g2_att = (const float*)d_in[22];
    const float* g2_bias= (const float*)d_in[23];
    const float* ah_w1  = (const float*)d_in[24];
    const float* ah_b1  = (const float*)d_in[25];
    const float* ah_w2  = (const float*)d_in[26];
    const float* ah_b2  = (const float*)d_in[27];
    const float* dec_w1 = (const float*)d_in[28];
    const float* dec_b1 = (const float*)d_in[29];
    const float* dec_w2 = (const float*)d_in[30];
    const float* dec_b2 = (const float*)d_in[31];

    float* out      = (float*)d_out;
    float* predsOut = out;
    float* Aout     = out + KC*PRED_DIM;
    float* assignO  = Aout + (size_t)NN*NN;

    float *h0, *h1, *h2, *bA, *bB, *tmp;
    cudaGetSymbolAddress((void**)&h0,  g_h0);
    cudaGetSymbolAddress((void**)&h1,  g_h1);
    cudaGetSymbolAddress((void**)&h2,  g_h2);
    cudaGetSymbolAddress((void**)&bA,  g_bufA);
    cudaGetSymbolAddress((void**)&bB,  g_bufB);
    cudaGetSymbolAddress((void**)&tmp, g_tmp);

    // encoder
    enc1_kernel<<<(NN*HID+255)/256, 256>>>(x, pos, ntype, temb, enc_w1, enc_b1, tmp);
    gemm64_kernel<<<NN/4, 256>>>(tmp, enc_w2, enc_b2, h0, 0);

    // self-loop attrs + CSR histogram
    loop_zero_kernel<<<(NN*8+255)/256, 256>>>();
    loop_accum_kernel<<<EE/256, 256>>>(ei, ea);
    loop_fin_kernel<<<(NN*6+255)/256, 256>>>();
    csr_scan_kernel<<<1, 1024>>>();
    csr_scatter_kernel<<<EE/256, 256>>>(ei);

    // GAT layer 1 (relu)
    gemm64_dual_kernel<<<NN/4, 256>>>(h0, g1_wl, g1_bl, g1_wr, g1_br, bA, bB);
    gat_fused_kernel<<<NN, 128>>>(ei, ea, g1_we, g1_att, g1_bias, bA, bB, h1, 1);

    // GAT layer 2
    gemm64_dual_kernel<<<NN/4, 256>>>(h1, g2_wl, g2_bl, g2_wr, g2_br, bA, bB);
    gat_fused_kernel<<<NN, 128>>>(ei, ea, g2_we, g2_att, g2_bias, bA, bB, h2, 0);

    // association matrix
    gemm64_dual_kernel<<<NN/4, 256>>>(h2, ah_w1, ah_b1, ah_w1 + HID*HID, nullptr, bA, bB);
    assoc_kernel<<<dim3(NN/64, NN/64), 256>>>(bA, bB, ah_w2, ah_b2, Aout);

    // clustering + epilogue
    cluster_kernel<<<1, 1024>>>(Aout);
    assign_kernel<<<NN/256, 256>>>(Aout, assignO);
    feats_kernel<<<KC, 256>>>(assignO, h2);
    preds_kernel<<<KC, HID>>>(dec_w1, dec_b1, dec_w2, dec_b2, predsOut);
}

// round 15
// speedup vs baseline: 1.7367x; 1.7367x over previous
#include <cuda_runtime.h>
#include <math.h>

#define NN 2048
#define EE 65536
#define EP (EE + NN)
#define HID 64
#define HEADS 4
#define HD 16
#define KC 25
#define PRED_DIM 7

typedef unsigned long long ull;

__device__ float g_h0[NN*HID];
__device__ float g_h1[NN*HID];
__device__ float g_h2[NN*HID];
__device__ float g_bufA[NN*HID];
__device__ float g_bufB[NN*HID];
__device__ float g_tmp[NN*HID];
__device__ __align__(16) float g_acc[NN*HID];
__device__ float g_denom[NN*HEADS];
__device__ float g_loop[NN*6];
__device__ __align__(16) float g_sums[NN*8];
__device__ int   g_idx[KC];
__device__ float g_feats[KC*HID];

// ---- packed f32x2 ----
__device__ __forceinline__ ull px2_add(ull a, ull b){
    ull r; asm("add.rn.f32x2 %0,%1,%2;" : "=l"(r) : "l"(a), "l"(b)); return r;
}
__device__ __forceinline__ ull px2_fma(ull a, ull b, ull c){
    ull r; asm("fma.rn.f32x2 %0,%1,%2,%3;" : "=l"(r) : "l"(a), "l"(b), "l"(c)); return r;
}
__device__ __forceinline__ ull px2_dup(float x){
    ull r; asm("mov.b64 %0,{%1,%1};" : "=l"(r) : "f"(x)); return r;
}

#define RED4(ptr, a,b,c,d) \
    asm volatile("red.global.add.v4.f32 [%0], {%1,%2,%3,%4};" \
                 :: "l"(ptr), "f"(a), "f"(b), "f"(c), "f"(d) : "memory")

// ---- JAX threefry2x32 ----
__device__ __forceinline__ void tf2x32(unsigned k0, unsigned k1, unsigned x0, unsigned x1,
                                       unsigned& o0, unsigned& o1){
    unsigned ks2 = k0 ^ k1 ^ 0x1BD11BDAu;
    x0 += k0; x1 += k1;
#define TFR(r) { x0 += x1; x1 = (x1 << (r)) | (x1 >> (32 - (r))); x1 ^= x0; }
    TFR(13) TFR(15) TFR(26) TFR(6)
    x0 += k1; x1 += ks2 + 1u;
    TFR(17) TFR(29) TFR(16) TFR(24)
    x0 += ks2; x1 += k0 + 2u;
    TFR(13) TFR(15) TFR(26) TFR(6)
    x0 += k0; x1 += k1 + 3u;
    TFR(17) TFR(29) TFR(16) TFR(24)
    x0 += k1; x1 += ks2 + 4u;
    TFR(13) TFR(15) TFR(26) TFR(6)
    x0 += ks2; x1 += k0 + 5u;
#undef TFR
    o0 = x0; o1 = x1;
}
__device__ __forceinline__ unsigned tf_bits32(unsigned k0, unsigned k1, unsigned i){
    unsigned o0, o1;
    tf2x32(k0, k1, 0u, i, o0, o1);
    return o0 ^ o1;
}
__device__ __forceinline__ float gumbel_from_bits(unsigned b){
    const float TINY = 1.17549435e-38f;
    float f = __uint_as_float((b >> 9) | 0x3f800000u) - 1.0f;
    float u = fmaxf(TINY, f*(1.0f - TINY) + TINY);
    return -logf(-logf(u));
}

// ---- encoder L1 ----
__global__ void enc1_kernel(const float* __restrict__ x, const float* __restrict__ pos,
                            const int* __restrict__ ntype, const float* __restrict__ temb,
                            const float* __restrict__ w1, const float* __restrict__ b1,
                            float* __restrict__ out){
    __shared__ float ws[15*HID];
    for (int i = threadIdx.x; i < 15*HID; i += blockDim.x) ws[i] = w1[i];
    __syncthreads();
    int idx = blockIdx.x*blockDim.x + threadIdx.x;
    if (idx >= NN*HID) return;
    int n = idx >> 6, c = idx & 63;
    float nf[15];
    nf[0]=x[n*4+0]; nf[1]=x[n*4+1]; nf[2]=x[n*4+2]; nf[3]=x[n*4+3];
    nf[4]=pos[n*3+0]; nf[5]=pos[n*3+1]; nf[6]=pos[n*3+2];
    int t = ntype[n];
    #pragma unroll
    for (int d=0; d<8; d++) nf[7+d] = temb[t*8+d];
    float acc = b1[c];
    #pragma unroll
    for (int d=0; d<15; d++) acc += nf[d]*ws[d*HID+c];
    out[idx] = fmaxf(acc, 0.f);
}

// ---- single [N,64]x[64,64] ----
__global__ void gemm64_kernel(const float* __restrict__ in, const float* __restrict__ w,
                              const float* __restrict__ b, float* __restrict__ out, int act){
    __shared__ float ws[HID*HID];
    __shared__ float ins[4][HID];
    int tid = threadIdx.x;
    for (int i = tid; i < HID*HID; i += 256) ws[i] = w[i];
    int r = tid >> 6, c = tid & 63;
    int row = blockIdx.x*4 + r;
    ins[r][c] = in[row*HID + c];
    __syncthreads();
    float acc = b ? b[c] : 0.f;
    #pragma unroll
    for (int k=0;k<HID;k++) acc += ins[r][k]*ws[k*HID+c];
    if (act) acc = fmaxf(acc, 0.f);
    out[row*HID+c] = acc;
}

// ---- dual [N,64]x[64,64] ----
__global__ void gemm64_dual_kernel(const float* __restrict__ in,
                                   const float* __restrict__ wA, const float* __restrict__ bA,
                                   const float* __restrict__ wB, const float* __restrict__ bB,
                                   float* __restrict__ oA, float* __restrict__ oB){
    __shared__ float wsA[HID*HID];
    __shared__ float wsB[HID*HID];
    __shared__ float ins[4][HID];
    int tid = threadIdx.x;
    for (int i = tid; i < HID*HID; i += 256){ wsA[i] = wA[i]; wsB[i] = wB[i]; }
    int r = tid >> 6, c = tid & 63;
    int row = blockIdx.x*4 + r;
    ins[r][c] = in[row*HID + c];
    __syncthreads();
    float aA = bA ? bA[c] : 0.f;
    float aB = bB ? bB[c] : 0.f;
    #pragma unroll
    for (int k=0;k<HID;k++){
        float v = ins[r][k];
        aA += v*wsA[k*HID+c];
        aB += v*wsB[k*HID+c];
    }
    oA[row*HID+c] = aA;
    oB[row*HID+c] = aB;
}

// ---- self-loop attrs ----
__global__ void loop_zero_kernel(){
    int i = blockIdx.x*blockDim.x+threadIdx.x;
    if (i < NN*8) g_sums[i]=0.f;
}
__global__ void loop_accum_kernel(const int* __restrict__ ei, const float* __restrict__ ea){
    int e = blockIdx.x*blockDim.x+threadIdx.x;
    if (e >= EE) return;
    int dst = ei[EE + e];
    float2 e01 = *(const float2*)(ea + e*6);
    float2 e23 = *(const float2*)(ea + e*6 + 2);
    float2 e45 = *(const float2*)(ea + e*6 + 4);
    float* p = &g_sums[dst*8];
    RED4(p,   e01.x, e01.y, e23.x, e23.y);
    RED4(p+4, e45.x, e45.y, 1.0f, 0.0f);
}
__global__ void loop_fin_kernel(){
    int i = blockIdx.x*blockDim.x+threadIdx.x;
    if (i >= NN*6) return;
    int n = i/6, d = i%6;
    g_loop[i] = g_sums[n*8+d] / fmaxf(g_sums[n*8+6], 1.f);
}

// ---- GATv2 ----
__global__ void gat_init_kernel(){
    int i = blockIdx.x*blockDim.x+threadIdx.x;
    if (i < NN*HID) g_acc[i]=0.f;
    if (i < NN*HEADS) g_denom[i]=0.f;
}

// fused logits+exp+accumulate: softmax shift-invariance (logits are O(3), exp safe)
__global__ void gat_pass12_kernel(const int* __restrict__ ei, const float* __restrict__ ea,
                                  const float* __restrict__ we, const float* __restrict__ att,
                                  const float* __restrict__ xl, const float* __restrict__ xr){
    __shared__ float wes[6*HID];
    __shared__ float atts[HID];
    for (int i=threadIdx.x;i<6*HID;i+=blockDim.x) wes[i]=we[i];
    if (threadIdx.x < HID) atts[threadIdx.x]=att[threadIdx.x];
    __syncthreads();
    int gid = blockIdx.x*blockDim.x+threadIdx.x;
    if (gid >= EP*HEADS) return;
    int e = gid >> 2, h = gid & 3;
    int src, dst;
    float eav[6];
    if (e < EE){
        src = ei[e]; dst = ei[EE+e];
        float2 a01 = *(const float2*)(ea + e*6);
        float2 a23 = *(const float2*)(ea + e*6 + 2);
        float2 a45 = *(const float2*)(ea + e*6 + 4);
        eav[0]=a01.x; eav[1]=a01.y; eav[2]=a23.x; eav[3]=a23.y; eav[4]=a45.x; eav[5]=a45.y;
    } else {
        src = dst = e - EE;
        float2 a01 = *(const float2*)(g_loop + src*6);
        float2 a23 = *(const float2*)(g_loop + src*6 + 2);
        float2 a45 = *(const float2*)(g_loop + src*6 + 4);
        eav[0]=a01.x; eav[1]=a01.y; eav[2]=a23.x; eav[3]=a23.y; eav[4]=a45.x; eav[5]=a45.y;
    }
    int base = h*HD;
    const float4* xl4 = (const float4*)(xl + src*HID + base);
    const float4* xr4 = (const float4*)(xr + dst*HID + base);
    float lv[16], xlv[16];
    #pragma unroll
    for (int q=0;q<4;q++){
        float4 L = xl4[q], R = xr4[q];
        xlv[q*4+0]=L.x; xlv[q*4+1]=L.y; xlv[q*4+2]=L.z; xlv[q*4+3]=L.w;
        lv[q*4+0]=L.x+R.x; lv[q*4+1]=L.y+R.y; lv[q*4+2]=L.z+R.z; lv[q*4+3]=L.w+R.w;
    }
    float lo = 0.f;
    #pragma unroll
    for (int k=0;k<HD;k++){
        float v = lv[k];
        #pragma unroll
        for (int d=0;d<6;d++) v += eav[d]*wes[d*HID+base+k];
        v = (v > 0.f) ? v : 0.2f*v;
        lo += v*atts[base+k];
    }
    float ex = expf(lo);
    atomicAdd(&g_denom[dst*HEADS+h], ex);
    float* accp = g_acc + dst*HID + base;
    #pragma unroll
    for (int q=0;q<4;q++){
        RED4(accp + q*4, xlv[q*4+0]*ex, xlv[q*4+1]*ex, xlv[q*4+2]*ex, xlv[q*4+3]*ex);
    }
}

__global__ void gat_pass3_kernel(const float* __restrict__ bias, float* __restrict__ hout, int act){
    int i = blockIdx.x*blockDim.x+threadIdx.x;
    if (i >= NN*HID) return;
    int n = i >> 6, c = i & 63;
    float v = g_acc[i] / g_denom[n*HEADS + (c>>4)] + bias[c];
    if (act) v = fmaxf(v, 0.f);
    hout[i] = v;
}

// ---- association matrix: transposed smem + packed f32x2 ----
__global__ void __launch_bounds__(256) assoc_kernel(
        const float* __restrict__ si, const float* __restrict__ sj,
        const float* __restrict__ w2, const float* __restrict__ b2,
        float* __restrict__ A){
    __shared__ __align__(16) float sis[64][68];
    __shared__ __align__(16) float sjs[64][68];
    __shared__ float w2h[64];
    int tid = threadIdx.x;
    int bi = blockIdx.y*64, bj = blockIdx.x*64;
    for (int i=tid;i<64*64;i+=256){
        int r = i >> 6, c = i & 63;
        sis[c][r] = si[(bi+r)*HID + c];
        sjs[c][r] = sj[(bj+r)*HID + c];
    }
    if (tid < 64) w2h[tid] = 0.5f*w2[tid];
    __syncthreads();
    int tx = tid & 31, ty = tid >> 5;
    int ib = 8*ty, jb = 2*tx;
    const ull MASK = 0x7FFFFFFF7FFFFFFFULL;
    ull acc[4][2];
    #pragma unroll
    for (int p=0;p<4;p++){ acc[p][0]=0ULL; acc[p][1]=0ULL; }
    #pragma unroll 8
    for (int c=0;c<64;c++){
        double2 A01 = *(const double2*)&sis[c][ib];
        double2 A23 = *(const double2*)&sis[c][ib+4];
        ull ap[4] = { __double_as_longlong(A01.x), __double_as_longlong(A01.y),
                      __double_as_longlong(A23.x), __double_as_longlong(A23.y) };
        ull pv0 = px2_dup(sjs[c][jb]);
        ull pv1 = px2_dup(sjs[c][jb+1]);
        ull pw  = px2_dup(w2h[c]);
        #pragma unroll
        for (int p=0;p<4;p++){
            ull t0 = px2_add(ap[p], pv0);
            t0 = px2_add(t0, t0 & MASK);
            acc[p][0] = px2_fma(t0, pw, acc[p][0]);
            ull t1 = px2_add(ap[p], pv1);
            t1 = px2_add(t1, t1 & MASK);
            acc[p][1] = px2_fma(t1, pw, acc[p][1]);
        }
    }
    float b2v = b2[0];
    #pragma unroll
    for (int p=0;p<4;p++){
        float o00 = __uint_as_float((unsigned)(acc[p][0]));
        float o01 = __uint_as_float((unsigned)(acc[p][0]>>32));
        float o10 = __uint_as_float((unsigned)(acc[p][1]));
        float o11 = __uint_as_float((unsigned)(acc[p][1]>>32));
        int i0 = bi + ib + 2*p;
        size_t r0o = (size_t)i0*NN + bj + jb;
        size_t r1o = (size_t)(i0+1)*NN + bj + jb;
        A[r0o]   = 1.f/(1.f+expf(-(o00+b2v)));
        A[r0o+1] = 1.f/(1.f+expf(-(o10+b2v)));
        A[r1o]   = 1.f/(1.f+expf(-(o01+b2v)));
        A[r1o+1] = 1.f/(1.f+expf(-(o11+b2v)));
    }
}

// ---- soft clustering (VERBATIM; do not touch) ----
__global__ void __launch_bounds__(1024) cluster_kernel(const float* __restrict__ A){
    __shared__ float s_mind[NN];
    __shared__ float s_wv[32];
    __shared__ int   s_wi[32];
    __shared__ unsigned s_k0[KC-1], s_k1[KC-1];
    __shared__ int s_nxt;
    __shared__ float s_inv;
    __shared__ unsigned s_kq0, s_kq1;
    int tid = threadIdx.x;
    int lane = tid & 31, wid = tid >> 5;

    if (tid == 0){
        unsigned kf0,kf1, kq0,kq1;
        tf2x32(0u,42u, 0u,0u, kf0,kf1);
        tf2x32(0u,42u, 0u,1u, kq0,kq1);
        s_kq0 = kq0; s_kq1 = kq1;
        unsigned s2_0, s2_1;
        tf2x32(kf0, kf1, 0u, 1u, s2_0, s2_1);
        unsigned lower = tf_bits32(s2_0, s2_1, 0u);
        int first = (int)(lower % (unsigned)NN);
        s_nxt = first;
        g_idx[0] = first;
    }
    __syncthreads();
    if (tid < KC-1){
        unsigned o0,o1;
        tf2x32(s_kq0, s_kq1, 0u, (unsigned)tid, o0, o1);
        s_k0[tid]=o0; s_k1[tid]=o1;
    }
    __syncthreads();
    {
        int first = s_nxt;
        s_mind[tid]      = 1.0f - A[(size_t)first*NN + tid];
        s_mind[tid+1024] = 1.0f - A[(size_t)first*NN + tid + 1024];
    }
    __syncthreads();

    for (int step=0; step<KC-1; step++){
        float s = s_mind[tid] + s_mind[tid+1024];
        #pragma unroll
        for (int o=16;o>0;o>>=1) s += __shfl_down_sync(0xffffffffu, s, o);
        if (lane==0) s_wv[wid]=s;
        __syncthreads();
        if (wid==0){
            float t = s_wv[lane];
            #pragma unroll
            for (int o=16;o>0;o>>=1) t += __shfl_down_sync(0xffffffffu, t, o);
            if (lane==0) s_inv = 1.0f/(t + 1e-8f);
        }
        __syncthreads();
        float inv = s_inv;
        unsigned b0 = tf_bits32(s_k0[step], s_k1[step], (unsigned)tid);
        unsigned b1 = tf_bits32(s_k0[step], s_k1[step], (unsigned)(tid+1024));
        float sc0 = logf(fmaxf(s_mind[tid]*inv,      1e-30f)) + gumbel_from_bits(b0);
        float sc1 = logf(fmaxf(s_mind[tid+1024]*inv, 1e-30f)) + gumbel_from_bits(b1);
        float bv; int bi;
        if (sc0 >= sc1){ bv = sc0; bi = tid; } else { bv = sc1; bi = tid + 1024; }
        #pragma unroll
        for (int o=16;o>0;o>>=1){
            float ov = __shfl_down_sync(0xffffffffu, bv, o);
            int   oi = __shfl_down_sync(0xffffffffu, bi, o);
            if (ov > bv || (ov == bv && oi < bi)){ bv = ov; bi = oi; }
        }
        if (lane==0){ s_wv[wid]=bv; s_wi[wid]=bi; }
        __syncthreads();
        if (wid==0){
            float v = s_wv[lane]; int ix = s_wi[lane];
            #pragma unroll
            for (int o=16;o>0;o>>=1){
                float ov = __shfl_down_sync(0xffffffffu, v, o);
                int   oi = __shfl_down_sync(0xffffffffu, ix, o);
                if (ov > v || (ov == v && oi < ix)){ v = ov; ix = oi; }
            }
            if (lane==0){ s_nxt = ix; g_idx[step+1] = ix; }
        }
        __syncthreads();
        int nxt = s_nxt;
        s_mind[tid]      = fminf(s_mind[tid],      1.0f - A[(size_t)nxt*NN + tid]);
        s_mind[tid+1024] = fminf(s_mind[tid+1024], 1.0f - A[(size_t)nxt*NN + tid + 1024]);
        __syncthreads();
    }
}

// ---- assign ----
__global__ void assign_kernel(const float* __restrict__ A, float* __restrict__ assign){
    __shared__ int idxs[KC];
    if (threadIdx.x < KC) idxs[threadIdx.x] = g_idx[threadIdx.x];
    __syncthreads();
    int n = blockIdx.x*blockDim.x + threadIdx.x;
    if (n >= NN) return;
    float v[KC];
    float mx = -3.4e38f;
    #pragma unroll
    for (int k=0;k<KC;k++){
        v[k] = A[(size_t)n*NN + idxs[k]] * 10.0f;
        mx = fmaxf(mx, v[k]);
    }
    float sum = 0.f;
    #pragma unroll
    for (int k=0;k<KC;k++){ v[k] = expf(v[k]-mx); sum += v[k]; }
    float invs = 1.0f/sum;
    #pragma unroll
    for (int k=0;k<KC;k++) assign[n*KC+k] = v[k]*invs;
}

// ---- feats ----
__global__ void feats_kernel(const float* __restrict__ assign, const float* __restrict__ h){
    int k = blockIdx.x;
    int tid = threadIdx.x;
    int c = tid & 63, g = tid >> 6;
    __shared__ float a_s[256];
    __shared__ float part[4][HID];
    float acc = 0.f;
    for (int n0=0; n0<NN; n0+=256){
        __syncthreads();
        a_s[tid] = assign[(n0+tid)*KC + k];
        __syncthreads();
        for (int nn=g; nn<256; nn+=4)
            acc += a_s[nn]*h[(size_t)(n0+nn)*HID + c];
    }
    part[g][c] = acc;
    __syncthreads();
    if (g == 0)
        g_feats[k*HID+c] = part[0][c]+part[1][c]+part[2][c]+part[3][c];
}

// ---- preds ----
__global__ void preds_kernel(const float* __restrict__ w1, const float* __restrict__ b1,
                             const float* __restrict__ w2, const float* __restrict__ b2,
                             float* __restrict__ preds){
    __shared__ float hid[HID];
    int k = blockIdx.x, c = threadIdx.x;
    float acc = b1[c];
    #pragma unroll
    for (int d=0;d<HID;d++) acc += g_feats[k*HID+d]*w1[d*HID+c];
    hid[c] = fmaxf(acc, 0.f);
    __syncthreads();
    if (c < PRED_DIM){
        float p = b2[c];
        #pragma unroll
        for (int d=0;d<HID;d++) p += hid[d]*w2[d*PRED_DIM+c];
        preds[k*PRED_DIM+c] = p;
    }
}

extern "C" void kernel_launch(void* const* d_in, const int* in_sizes, int n_in,
                              void* d_out, int out_size) {
    const float* x        = (const float*)d_in[0];
    const float* pos      = (const float*)d_in[1];
    const int*   ntype    = (const int*)d_in[2];
    const int*   ei       = (const int*)d_in[3];
    const float* ea       = (const float*)d_in[4];
    const float* temb     = (const float*)d_in[5];
    const float* enc_w1   = (const float*)d_in[6];
    const float* enc_b1   = (const float*)d_in[7];
    const float* enc_w2   = (const float*)d_in[8];
    const float* enc_b2   = (const float*)d_in[9];
    const float* g1_wl  = (const float*)d_in[10];
    const float* g1_bl  = (const float*)d_in[11];
    const float* g1_wr  = (const float*)d_in[12];
    const float* g1_br  = (const float*)d_in[13];
    const float* g1_we  = (const float*)d_in[14];
    const float* g1_att = (const float*)d_in[15];
    const float* g1_bias= (const float*)d_in[16];
    const float* g2_wl  = (const float*)d_in[17];
    const float* g2_bl  = (const float*)d_in[18];
    const float* g2_wr  = (const float*)d_in[19];
    const float* g2_br  = (const float*)d_in[20];
    const float* g2_we  = (const float*)d_in[21];
    const float* g2_att = (const float*)d_in[22];
    const float* g2_bias= (const float*)d_in[23];
    const float* ah_w1  = (const float*)d_in[24];
    const float* ah_b1  = (const float*)d_in[25];
    const float* ah_w2  = (const float*)d_in[26];
    const float* ah_b2  = (const float*)d_in[27];
    const float* dec_w1 = (const float*)d_in[28];
    const float* dec_b1 = (const float*)d_in[29];
    const float* dec_w2 = (const float*)d_in[30];
    const float* dec_b2 = (const float*)d_in[31];

    float* out      = (float*)d_out;
    float* predsOut = out;
    float* Aout     = out + KC*PRED_DIM;
    float* assignO  = Aout + (size_t)NN*NN;

    float *h0, *h1, *h2, *bA, *bB, *tmp;
    cudaGetSymbolAddress((void**)&h0,  g_h0);
    cudaGetSymbolAddress((void**)&h1,  g_h1);
    cudaGetSymbolAddress((void**)&h2,  g_h2);
    cudaGetSymbolAddress((void**)&bA,  g_bufA);
    cudaGetSymbolAddress((void**)&bB,  g_bufB);
    cudaGetSymbolAddress((void**)&tmp, g_tmp);

    const int EHT = ((EP*HEADS)+255)/256;

    enc1_kernel<<<(NN*HID+255)/256, 256>>>(x, pos, ntype, temb, enc_w1, enc_b1, tmp);
    gemm64_kernel<<<NN/4, 256>>>(tmp, enc_w2, enc_b2, h0, 0);

    loop_zero_kernel<<<(NN*8+255)/256, 256>>>();
    loop_accum_kernel<<<EE/256, 256>>>(ei, ea);
    loop_fin_kernel<<<(NN*6+255)/256, 256>>>();

    // GAT layer 1 (relu)
    gemm64_dual_kernel<<<NN/4, 256>>>(h0, g1_wl, g1_bl, g1_wr, g1_br, bA, bB);
    gat_init_kernel<<<(NN*HID+255)/256, 256>>>();
    gat_pass12_kernel<<<EHT, 256>>>(ei, ea, g1_we, g1_att, bA, bB);
    gat_pass3_kernel<<<(NN*HID+255)/256, 256>>>(g1_bias, h1, 1);

    // GAT layer 2
    gemm64_dual_kernel<<<NN/4, 256>>>(h1, g2_wl, g2_bl, g2_wr, g2_br, bA, bB);
    gat_init_kernel<<<(NN*HID+255)/256, 256>>>();
    gat_pass12_kernel<<<EHT, 256>>>(ei, ea, g2_we, g2_att, bA, bB);
    gat_pass3_kernel<<<(NN*HID+255)/256, 256>>>(g2_bias, h2, 0);

    // association matrix
    gemm64_dual_kernel<<<NN/4, 256>>>(h2, ah_w1, ah_b1, ah_w1 + HID*HID, nullptr, bA, bB);
    assoc_kernel<<<dim3(NN/64, NN/64), 256>>>(bA, bB, ah_w2, ah_b2, Aout);

    // clustering + epilogue
    cluster_kernel<<<1, 1024>>>(Aout);
    assign_kernel<<<NN/256, 256>>>(Aout, assignO);
    feats_kernel<<<KC, 256>>>(assignO, h2);
    preds_kernel<<<KC, HID>>>(dec_w1, dec_b1, dec_w2, dec_b2, predsOut);
}

// round 16
// speedup vs baseline: 1.7943x; 1.0332x over previous
#include <cuda_runtime.h>
#include <math.h>

#define NN 2048
#define EE 65536
#define EP (EE + NN)
#define HID 64
#define HEADS 4
#define HD 16
#define KC 25
#define PRED_DIM 7

typedef unsigned long long ull;

__device__ float g_h0[NN*HID];
__device__ float g_h2[NN*HID];
__device__ float g_bufA[NN*HID];
__device__ float g_bufB[NN*HID];
__device__ __align__(16) float g_acc1[NN*HID];
__device__ __align__(16) float g_acc2[NN*HID];
__device__ float g_denom1[NN*HEADS];
__device__ float g_denom2[NN*HEADS];
__device__ float g_loop[NN*6];
__device__ __align__(16) float g_sums[NN*8];
__device__ int   g_idx[KC];
__device__ float g_feats[KC*HID];

// ---- packed f32x2 ----
__device__ __forceinline__ ull px2_add(ull a, ull b){
    ull r; asm("add.rn.f32x2 %0,%1,%2;" : "=l"(r) : "l"(a), "l"(b)); return r;
}
__device__ __forceinline__ ull px2_fma(ull a, ull b, ull c){
    ull r; asm("fma.rn.f32x2 %0,%1,%2,%3;" : "=l"(r) : "l"(a), "l"(b), "l"(c)); return r;
}
__device__ __forceinline__ ull px2_dup(float x){
    ull r; asm("mov.b64 %0,{%1,%1};" : "=l"(r) : "f"(x)); return r;
}

#define RED4(ptr, a,b,c,d) \
    asm volatile("red.global.add.v4.f32 [%0], {%1,%2,%3,%4};" \
                 :: "l"(ptr), "f"(a), "f"(b), "f"(c), "f"(d) : "memory")

// ---- JAX threefry2x32 ----
__device__ __forceinline__ void tf2x32(unsigned k0, unsigned k1, unsigned x0, unsigned x1,
                                       unsigned& o0, unsigned& o1){
    unsigned ks2 = k0 ^ k1 ^ 0x1BD11BDAu;
    x0 += k0; x1 += k1;
#define TFR(r) { x0 += x1; x1 = (x1 << (r)) | (x1 >> (32 - (r))); x1 ^= x0; }
    TFR(13) TFR(15) TFR(26) TFR(6)
    x0 += k1; x1 += ks2 + 1u;
    TFR(17) TFR(29) TFR(16) TFR(24)
    x0 += ks2; x1 += k0 + 2u;
    TFR(13) TFR(15) TFR(26) TFR(6)
    x0 += k0; x1 += k1 + 3u;
    TFR(17) TFR(29) TFR(16) TFR(24)
    x0 += k1; x1 += ks2 + 4u;
    TFR(13) TFR(15) TFR(26) TFR(6)
    x0 += ks2; x1 += k0 + 5u;
#undef TFR
    o0 = x0; o1 = x1;
}
__device__ __forceinline__ unsigned tf_bits32(unsigned k0, unsigned k1, unsigned i){
    unsigned o0, o1;
    tf2x32(k0, k1, 0u, i, o0, o1);
    return o0 ^ o1;
}
__device__ __forceinline__ float gumbel_from_bits(unsigned b){
    const float TINY = 1.17549435e-38f;
    float f = __uint_as_float((b >> 9) | 0x3f800000u) - 1.0f;
    float u = fmaxf(TINY, f*(1.0f - TINY) + TINY);
    return -logf(-logf(u));
}

// ---- fused encoder: relu(nf@w1+b1)@w2+b2, grid NN/4, 256 thr ----
__global__ void enc_fused_kernel(const float* __restrict__ x, const float* __restrict__ pos,
                                 const int* __restrict__ ntype, const float* __restrict__ temb,
                                 const float* __restrict__ w1, const float* __restrict__ b1,
                                 const float* __restrict__ w2, const float* __restrict__ b2,
                                 float* __restrict__ out){
    __shared__ float w1s[15*HID];
    __shared__ float w2s[HID*HID];
    __shared__ float hid[4][HID];
    int tid = threadIdx.x;
    for (int i = tid; i < 15*HID; i += 256) w1s[i] = w1[i];
    for (int i = tid; i < HID*HID; i += 256) w2s[i] = w2[i];
    int r = tid >> 6, c = tid & 63;
    int n = blockIdx.x*4 + r;
    float nf[15];
    nf[0]=x[n*4+0]; nf[1]=x[n*4+1]; nf[2]=x[n*4+2]; nf[3]=x[n*4+3];
    nf[4]=pos[n*3+0]; nf[5]=pos[n*3+1]; nf[6]=pos[n*3+2];
    int t = ntype[n];
    #pragma unroll
    for (int d=0; d<8; d++) nf[7+d] = temb[t*8+d];
    __syncthreads();
    float acc = b1[c];
    #pragma unroll
    for (int d=0; d<15; d++) acc += nf[d]*w1s[d*HID+c];
    hid[r][c] = fmaxf(acc, 0.f);
    __syncthreads();
    float o = b2[c];
    #pragma unroll
    for (int k=0;k<HID;k++) o += hid[r][k]*w2s[k*HID+c];
    out[n*HID+c] = o;
}

// ---- init: zero all accumulators in one kernel ----
__global__ void init_all_kernel(){
    int i = blockIdx.x*blockDim.x+threadIdx.x;
    if (i < NN*HID){ g_acc1[i]=0.f; g_acc2[i]=0.f; }
    if (i < NN*8) g_sums[i]=0.f;
    if (i < NN*HEADS){ g_denom1[i]=0.f; g_denom2[i]=0.f; }
}

// ---- self-loop attrs ----
__global__ void loop_accum_kernel(const int* __restrict__ ei, const float* __restrict__ ea){
    int e = blockIdx.x*blockDim.x+threadIdx.x;
    if (e >= EE) return;
    int dst = ei[EE + e];
    float2 e01 = *(const float2*)(ea + e*6);
    float2 e23 = *(const float2*)(ea + e*6 + 2);
    float2 e45 = *(const float2*)(ea + e*6 + 4);
    float* p = &g_sums[dst*8];
    RED4(p,   e01.x, e01.y, e23.x, e23.y);
    RED4(p+4, e45.x, e45.y, 1.0f, 0.0f);
}
__global__ void loop_fin_kernel(){
    int i = blockIdx.x*blockDim.x+threadIdx.x;
    if (i >= NN*6) return;
    int n = i/6, d = i%6;
    g_loop[i] = g_sums[n*8+d] / fmaxf(g_sums[n*8+6], 1.f);
}

// ---- plain dual GEMM (layer-1 entry: reads h0 directly) ----
__global__ void gemm64_dual_kernel(const float* __restrict__ in,
                                   const float* __restrict__ wA, const float* __restrict__ bA,
                                   const float* __restrict__ wB, const float* __restrict__ bB,
                                   float* __restrict__ oA, float* __restrict__ oB){
    __shared__ float wsA[HID*HID];
    __shared__ float wsB[HID*HID];
    __shared__ float ins[4][HID];
    int tid = threadIdx.x;
    for (int i = tid; i < HID*HID; i += 256){ wsA[i] = wA[i]; wsB[i] = wB[i]; }
    int r = tid >> 6, c = tid & 63;
    int row = blockIdx.x*4 + r;
    ins[r][c] = in[row*HID + c];
    __syncthreads();
    float aA = bA ? bA[c] : 0.f;
    float aB = bB ? bB[c] : 0.f;
    #pragma unroll
    for (int k=0;k<HID;k++){
        float v = ins[r][k];
        aA += v*wsA[k*HID+c];
        aB += v*wsB[k*HID+c];
    }
    oA[row*HID+c] = aA;
    oB[row*HID+c] = aB;
}

// ---- dual GEMM with fused GAT epilogue input: in = act?(acc/denom + gbias) ----
// Also optionally stores the normalized input to hstore.
__global__ void gemm64_dual_gat_kernel(const float* __restrict__ acc, const float* __restrict__ denom,
                                       const float* __restrict__ gbias, int act,
                                       const float* __restrict__ wA, const float* __restrict__ bA,
                                       const float* __restrict__ wB, const float* __restrict__ bB,
                                       float* __restrict__ oA, float* __restrict__ oB,
                                       float* __restrict__ hstore){
    __shared__ float wsA[HID*HID];
    __shared__ float wsB[HID*HID];
    __shared__ float ins[4][HID];
    int tid = threadIdx.x;
    for (int i = tid; i < HID*HID; i += 256){ wsA[i] = wA[i]; wsB[i] = wB[i]; }
    int r = tid >> 6, c = tid & 63;
    int row = blockIdx.x*4 + r;
    {
        float v = acc[row*HID+c] / denom[row*HEADS + (c>>4)] + gbias[c];
        if (act) v = fmaxf(v, 0.f);
        ins[r][c] = v;
        if (hstore) hstore[row*HID+c] = v;
    }
    __syncthreads();
    float aA = bA ? bA[c] : 0.f;
    float aB = bB ? bB[c] : 0.f;
    #pragma unroll
    for (int k=0;k<HID;k++){
        float v = ins[r][k];
        aA += v*wsA[k*HID+c];
        aB += v*wsB[k*HID+c];
    }
    oA[row*HID+c] = aA;
    oB[row*HID+c] = aB;
}

// ---- fused GAT edge pass (shift-free softmax; logits O(3), exp safe) ----
__global__ void gat_pass12_kernel(const int* __restrict__ ei, const float* __restrict__ ea,
                                  const float* __restrict__ we, const float* __restrict__ att,
                                  const float* __restrict__ xl, const float* __restrict__ xr,
                                  float* __restrict__ acc, float* __restrict__ denom){
    __shared__ float wes[6*HID];
    __shared__ float atts[HID];
    for (int i=threadIdx.x;i<6*HID;i+=blockDim.x) wes[i]=we[i];
    if (threadIdx.x < HID) atts[threadIdx.x]=att[threadIdx.x];
    __syncthreads();
    int gid = blockIdx.x*blockDim.x+threadIdx.x;
    if (gid >= EP*HEADS) return;
    int e = gid >> 2, h = gid & 3;
    int src, dst;
    float eav[6];
    if (e < EE){
        src = ei[e]; dst = ei[EE+e];
        float2 a01 = *(const float2*)(ea + e*6);
        float2 a23 = *(const float2*)(ea + e*6 + 2);
        float2 a45 = *(const float2*)(ea + e*6 + 4);
        eav[0]=a01.x; eav[1]=a01.y; eav[2]=a23.x; eav[3]=a23.y; eav[4]=a45.x; eav[5]=a45.y;
    } else {
        src = dst = e - EE;
        float2 a01 = *(const float2*)(g_loop + src*6);
        float2 a23 = *(const float2*)(g_loop + src*6 + 2);
        float2 a45 = *(const float2*)(g_loop + src*6 + 4);
        eav[0]=a01.x; eav[1]=a01.y; eav[2]=a23.x; eav[3]=a23.y; eav[4]=a45.x; eav[5]=a45.y;
    }
    int base = h*HD;
    const float4* xl4 = (const float4*)(xl + src*HID + base);
    const float4* xr4 = (const float4*)(xr + dst*HID + base);
    float lv[16], xlv[16];
    #pragma unroll
    for (int q=0;q<4;q++){
        float4 L = xl4[q], R = xr4[q];
        xlv[q*4+0]=L.x; xlv[q*4+1]=L.y; xlv[q*4+2]=L.z; xlv[q*4+3]=L.w;
        lv[q*4+0]=L.x+R.x; lv[q*4+1]=L.y+R.y; lv[q*4+2]=L.z+R.z; lv[q*4+3]=L.w+R.w;
    }
    float lo = 0.f;
    #pragma unroll
    for (int k=0;k<HD;k++){
        float v = lv[k];
        #pragma unroll
        for (int d=0;d<6;d++) v += eav[d]*wes[d*HID+base+k];
        v = (v > 0.f) ? v : 0.2f*v;
        lo += v*atts[base+k];
    }
    float ex = expf(lo);
    atomicAdd(&denom[dst*HEADS+h], ex);
    float* accp = acc + dst*HID + base;
    #pragma unroll
    for (int q=0;q<4;q++){
        RED4(accp + q*4, xlv[q*4+0]*ex, xlv[q*4+1]*ex, xlv[q*4+2]*ex, xlv[q*4+3]*ex);
    }
}

// ---- association matrix: transposed smem + packed f32x2 ----
__global__ void __launch_bounds__(256) assoc_kernel(
        const float* __restrict__ si, const float* __restrict__ sj,
        const float* __restrict__ w2, const float* __restrict__ b2,
        float* __restrict__ A){
    __shared__ __align__(16) float sis[64][68];
    __shared__ __align__(16) float sjs[64][68];
    __shared__ float w2h[64];
    int tid = threadIdx.x;
    int bi = blockIdx.y*64, bj = blockIdx.x*64;
    for (int i=tid;i<64*64;i+=256){
        int r = i >> 6, c = i & 63;
        sis[c][r] = si[(bi+r)*HID + c];
        sjs[c][r] = sj[(bj+r)*HID + c];
    }
    if (tid < 64) w2h[tid] = 0.5f*w2[tid];
    __syncthreads();
    int tx = tid & 31, ty = tid >> 5;
    int ib = 8*ty, jb = 2*tx;
    const ull MASK = 0x7FFFFFFF7FFFFFFFULL;
    ull acc[4][2];
    #pragma unroll
    for (int p=0;p<4;p++){ acc[p][0]=0ULL; acc[p][1]=0ULL; }
    #pragma unroll 8
    for (int c=0;c<64;c++){
        double2 A01 = *(const double2*)&sis[c][ib];
        double2 A23 = *(const double2*)&sis[c][ib+4];
        ull ap[4] = { __double_as_longlong(A01.x), __double_as_longlong(A01.y),
                      __double_as_longlong(A23.x), __double_as_longlong(A23.y) };
        ull pv0 = px2_dup(sjs[c][jb]);
        ull pv1 = px2_dup(sjs[c][jb+1]);
        ull pw  = px2_dup(w2h[c]);
        #pragma unroll
        for (int p=0;p<4;p++){
            ull t0 = px2_add(ap[p], pv0);
            t0 = px2_add(t0, t0 & MASK);
            acc[p][0] = px2_fma(t0, pw, acc[p][0]);
            ull t1 = px2_add(ap[p], pv1);
            t1 = px2_add(t1, t1 & MASK);
            acc[p][1] = px2_fma(t1, pw, acc[p][1]);
        }
    }
    float b2v = b2[0];
    #pragma unroll
    for (int p=0;p<4;p++){
        float o00 = __uint_as_float((unsigned)(acc[p][0]));
        float o01 = __uint_as_float((unsigned)(acc[p][0]>>32));
        float o10 = __uint_as_float((unsigned)(acc[p][1]));
        float o11 = __uint_as_float((unsigned)(acc[p][1]>>32));
        int i0 = bi + ib + 2*p;
        size_t r0o = (size_t)i0*NN + bj + jb;
        size_t r1o = (size_t)(i0+1)*NN + bj + jb;
        A[r0o]   = 1.f/(1.f+expf(-(o00+b2v)));
        A[r0o+1] = 1.f/(1.f+expf(-(o10+b2v)));
        A[r1o]   = 1.f/(1.f+expf(-(o01+b2v)));
        A[r1o+1] = 1.f/(1.f+expf(-(o11+b2v)));
    }
}

// ---- soft clustering (VERBATIM; do not touch) ----
__global__ void __launch_bounds__(1024) cluster_kernel(const float* __restrict__ A){
    __shared__ float s_mind[NN];
    __shared__ float s_wv[32];
    __shared__ int   s_wi[32];
    __shared__ unsigned s_k0[KC-1], s_k1[KC-1];
    __shared__ int s_nxt;
    __shared__ float s_inv;
    __shared__ unsigned s_kq0, s_kq1;
    int tid = threadIdx.x;
    int lane = tid & 31, wid = tid >> 5;

    if (tid == 0){
        unsigned kf0,kf1, kq0,kq1;
        tf2x32(0u,42u, 0u,0u, kf0,kf1);
        tf2x32(0u,42u, 0u,1u, kq0,kq1);
        s_kq0 = kq0; s_kq1 = kq1;
        unsigned s2_0, s2_1;
        tf2x32(kf0, kf1, 0u, 1u, s2_0, s2_1);
        unsigned lower = tf_bits32(s2_0, s2_1, 0u);
        int first = (int)(lower % (unsigned)NN);
        s_nxt = first;
        g_idx[0] = first;
    }
    __syncthreads();
    if (tid < KC-1){
        unsigned o0,o1;
        tf2x32(s_kq0, s_kq1, 0u, (unsigned)tid, o0, o1);
        s_k0[tid]=o0; s_k1[tid]=o1;
    }
    __syncthreads();
    {
        int first = s_nxt;
        s_mind[tid]      = 1.0f - A[(size_t)first*NN + tid];
        s_mind[tid+1024] = 1.0f - A[(size_t)first*NN + tid + 1024];
    }
    __syncthreads();

    for (int step=0; step<KC-1; step++){
        float s = s_mind[tid] + s_mind[tid+1024];
        #pragma unroll
        for (int o=16;o>0;o>>=1) s += __shfl_down_sync(0xffffffffu, s, o);
        if (lane==0) s_wv[wid]=s;
        __syncthreads();
        if (wid==0){
            float t = s_wv[lane];
            #pragma unroll
            for (int o=16;o>0;o>>=1) t += __shfl_down_sync(0xffffffffu, t, o);
            if (lane==0) s_inv = 1.0f/(t + 1e-8f);
        }
        __syncthreads();
        float inv = s_inv;
        unsigned b0 = tf_bits32(s_k0[step], s_k1[step], (unsigned)tid);
        unsigned b1 = tf_bits32(s_k0[step], s_k1[step], (unsigned)(tid+1024));
        float sc0 = logf(fmaxf(s_mind[tid]*inv,      1e-30f)) + gumbel_from_bits(b0);
        float sc1 = logf(fmaxf(s_mind[tid+1024]*inv, 1e-30f)) + gumbel_from_bits(b1);
        float bv; int bi;
        if (sc0 >= sc1){ bv = sc0; bi = tid; } else { bv = sc1; bi = tid + 1024; }
        #pragma unroll
        for (int o=16;o>0;o>>=1){
            float ov = __shfl_down_sync(0xffffffffu, bv, o);
            int   oi = __shfl_down_sync(0xffffffffu, bi, o);
            if (ov > bv || (ov == bv && oi < bi)){ bv = ov; bi = oi; }
        }
        if (lane==0){ s_wv[wid]=bv; s_wi[wid]=bi; }
        __syncthreads();
        if (wid==0){
            float v = s_wv[lane]; int ix = s_wi[lane];
            #pragma unroll
            for (int o=16;o>0;o>>=1){
                float ov = __shfl_down_sync(0xffffffffu, v, o);
                int   oi = __shfl_down_sync(0xffffffffu, ix, o);
                if (ov > v || (ov == v && oi < ix)){ v = ov; ix = oi; }
            }
            if (lane==0){ s_nxt = ix; g_idx[step+1] = ix; }
        }
        __syncthreads();
        int nxt = s_nxt;
        s_mind[tid]      = fminf(s_mind[tid],      1.0f - A[(size_t)nxt*NN + tid]);
        s_mind[tid+1024] = fminf(s_mind[tid+1024], 1.0f - A[(size_t)nxt*NN + tid + 1024]);
        __syncthreads();
    }
}

// ---- assign ----
__global__ void assign_kernel(const float* __restrict__ A, float* __restrict__ assign){
    __shared__ int idxs[KC];
    if (threadIdx.x < KC) idxs[threadIdx.x] = g_idx[threadIdx.x];
    __syncthreads();
    int n = blockIdx.x*blockDim.x + threadIdx.x;
    if (n >= NN) return;
    float v[KC];
    float mx = -3.4e38f;
    #pragma unroll
    for (int k=0;k<KC;k++){
        v[k] = A[(size_t)n*NN + idxs[k]] * 10.0f;
        mx = fmaxf(mx, v[k]);
    }
    float sum = 0.f;
    #pragma unroll
    for (int k=0;k<KC;k++){ v[k] = expf(v[k]-mx); sum += v[k]; }
    float invs = 1.0f/sum;
    #pragma unroll
    for (int k=0;k<KC;k++) assign[n*KC+k] = v[k]*invs;
}

// ---- feats ----
__global__ void feats_kernel(const float* __restrict__ assign, const float* __restrict__ h){
    int k = blockIdx.x;
    int tid = threadIdx.x;
    int c = tid & 63, g = tid >> 6;
    __shared__ float a_s[256];
    __shared__ float part[4][HID];
    float acc = 0.f;
    for (int n0=0; n0<NN; n0+=256){
        __syncthreads();
        a_s[tid] = assign[(n0+tid)*KC + k];
        __syncthreads();
        for (int nn=g; nn<256; nn+=4)
            acc += a_s[nn]*h[(size_t)(n0+nn)*HID + c];
    }
    part[g][c] = acc;
    __syncthreads();
    if (g == 0)
        g_feats[k*HID+c] = part[0][c]+part[1][c]+part[2][c]+part[3][c];
}

// ---- preds ----
__global__ void preds_kernel(const float* __restrict__ w1, const float* __restrict__ b1,
                             const float* __restrict__ w2, const float* __restrict__ b2,
                             float* __restrict__ preds){
    __shared__ float hid[HID];
    int k = blockIdx.x, c = threadIdx.x;
    float acc = b1[c];
    #pragma unroll
    for (int d=0;d<HID;d++) acc += g_feats[k*HID+d]*w1[d*HID+c];
    hid[c] = fmaxf(acc, 0.f);
    __syncthreads();
    if (c < PRED_DIM){
        float p = b2[c];
        #pragma unroll
        for (int d=0;d<HID;d++) p += hid[d]*w2[d*PRED_DIM+c];
        preds[k*PRED_DIM+c] = p;
    }
}

extern "C" void kernel_launch(void* const* d_in, const int* in_sizes, int n_in,
                              void* d_out, int out_size) {
    const float* x        = (const float*)d_in[0];
    const float* pos      = (const float*)d_in[1];
    const int*   ntype    = (const int*)d_in[2];
    const int*   ei       = (const int*)d_in[3];
    const float* ea       = (const float*)d_in[4];
    const float* temb     = (const float*)d_in[5];
    const float* enc_w1   = (const float*)d_in[6];
    const float* enc_b1   = (const float*)d_in[7];
    const float* enc_w2   = (const float*)d_in[8];
    const float* enc_b2   = (const float*)d_in[9];
    const float* g1_wl  = (const float*)d_in[10];
    const float* g1_bl  = (const float*)d_in[11];
    const float* g1_wr  = (const float*)d_in[12];
    const float* g1_br  = (const float*)d_in[13];
    const float* g1_we  = (const float*)d_in[14];
    const float* g1_att = (const float*)d_in[15];
    const float* g1_bias= (const float*)d_in[16];
    const float* g2_wl  = (const float*)d_in[17];
    const float* g2_bl  = (const float*)d_in[18];
    const float* g2_wr  = (const float*)d_in[19];
    const float* g2_br  = (const float*)d_in[20];
    const float* g2_we  = (const float*)d_in[21];
    const float* g2_att = (const float*)d_in[22];
    const float* g2_bias= (const float*)d_in[23];
    const float* ah_w1  = (const float*)d_in[24];
    const float* ah_b1  = (const float*)d_in[25];
    const float* ah_w2  = (const float*)d_in[26];
    const float* ah_b2  = (const float*)d_in[27];
    const float* dec_w1 = (const float*)d_in[28];
    const float* dec_b1 = (const float*)d_in[29];
    const float* dec_w2 = (const float*)d_in[30];
    const float* dec_b2 = (const float*)d_in[31];

    float* out      = (float*)d_out;
    float* predsOut = out;
    float* Aout     = out + KC*PRED_DIM;
    float* assignO  = Aout + (size_t)NN*NN;

    float *h0, *h2, *bA, *bB, *acc1, *acc2, *den1, *den2;
    cudaGetSymbolAddress((void**)&h0,   g_h0);
    cudaGetSymbolAddress((void**)&h2,   g_h2);
    cudaGetSymbolAddress((void**)&bA,   g_bufA);
    cudaGetSymbolAddress((void**)&bB,   g_bufB);
    cudaGetSymbolAddress((void**)&acc1, g_acc1);
    cudaGetSymbolAddress((void**)&acc2, g_acc2);
    cudaGetSymbolAddress((void**)&den1, g_denom1);
    cudaGetSymbolAddress((void**)&den2, g_denom2);

    const int EHT = ((EP*HEADS)+255)/256;

    init_all_kernel<<<(NN*HID+255)/256, 256>>>();
    enc_fused_kernel<<<NN/4, 256>>>(x, pos, ntype, temb, enc_w1, enc_b1, enc_w2, enc_b2, h0);

    loop_accum_kernel<<<EE/256, 256>>>(ei, ea);
    loop_fin_kernel<<<(NN*6+255)/256, 256>>>();

    // GAT layer 1
    gemm64_dual_kernel<<<NN/4, 256>>>(h0, g1_wl, g1_bl, g1_wr, g1_br, bA, bB);
    gat_pass12_kernel<<<EHT, 256>>>(ei, ea, g1_we, g1_att, bA, bB, acc1, den1);

    // GAT layer 2 (pass3 of layer 1 fused into this gemm's input load)
    gemm64_dual_gat_kernel<<<NN/4, 256>>>(acc1, den1, g1_bias, 1,
                                          g2_wl, g2_bl, g2_wr, g2_br, bA, bB, nullptr);
    gat_pass12_kernel<<<EHT, 256>>>(ei, ea, g2_we, g2_att, bA, bB, acc2, den2);

    // association matrix (pass3 of layer 2 fused; also materializes h2)
    gemm64_dual_gat_kernel<<<NN/4, 256>>>(acc2, den2, g2_bias, 0,
                                          ah_w1, ah_b1, ah_w1 + HID*HID, nullptr, bA, bB, h2);
    assoc_kernel<<<dim3(NN/64, NN/64), 256>>>(bA, bB, ah_w2, ah_b2, Aout);

    // clustering + epilogue
    cluster_kernel<<<1, 1024>>>(Aout);
    assign_kernel<<<NN/256, 256>>>(Aout, assignO);
    feats_kernel<<<KC, 256>>>(assignO, h2);
    preds_kernel<<<KC, HID>>>(dec_w1, dec_b1, dec_w2, dec_b2, predsOut);
}

// round 17
// speedup vs baseline: 1.9095x; 1.0642x over previous
#include <cuda_runtime.h>
#include <math.h>

#define NN 2048
#define EE 65536
#define NEP (EE + NN)
#define HID 64
#define HEADS 4
#define HD 16
#define KC 25
#define PRED_DIM 7

typedef unsigned long long ull;

__device__ float g_h0[NN*HID];
__device__ float g_h2[NN*HID];
__device__ float g_bufA[NN*HID];
__device__ float g_bufB[NN*HID];
__device__ __align__(16) float g_acc1[NN*HID];
__device__ __align__(16) float g_acc2[NN*HID];
__device__ float g_denom1[NN*HEADS];
__device__ float g_denom2[NN*HEADS];
__device__ __align__(16) float g_sums[NN*8];
__device__ int   g_idx[KC];
__device__ float g_feats[KC*HID];
__device__ int   g_cnt[NN];
__device__ int   g_rowptr[NN+1];
__device__ int   g_eids[NEP];
__device__ int   g_edst[NEP];

// ---- packed f32x2 ----
__device__ __forceinline__ ull px2_add(ull a, ull b){
    ull r; asm("add.rn.f32x2 %0,%1,%2;" : "=l"(r) : "l"(a), "l"(b)); return r;
}
__device__ __forceinline__ ull px2_fma(ull a, ull b, ull c){
    ull r; asm("fma.rn.f32x2 %0,%1,%2,%3;" : "=l"(r) : "l"(a), "l"(b), "l"(c)); return r;
}
__device__ __forceinline__ ull px2_dup(float x){
    ull r; asm("mov.b64 %0,{%1,%1};" : "=l"(r) : "f"(x)); return r;
}

#define RED4(ptr, a,b,c,d) \
    asm volatile("red.global.add.v4.f32 [%0], {%1,%2,%3,%4};" \
                 :: "l"(ptr), "f"(a), "f"(b), "f"(c), "f"(d) : "memory")

// ---- JAX threefry2x32 ----
__device__ __forceinline__ void tf2x32(unsigned k0, unsigned k1, unsigned x0, unsigned x1,
                                       unsigned& o0, unsigned& o1){
    unsigned ks2 = k0 ^ k1 ^ 0x1BD11BDAu;
    x0 += k0; x1 += k1;
#define TFR(r) { x0 += x1; x1 = (x1 << (r)) | (x1 >> (32 - (r))); x1 ^= x0; }
    TFR(13) TFR(15) TFR(26) TFR(6)
    x0 += k1; x1 += ks2 + 1u;
    TFR(17) TFR(29) TFR(16) TFR(24)
    x0 += ks2; x1 += k0 + 2u;
    TFR(13) TFR(15) TFR(26) TFR(6)
    x0 += k0; x1 += k1 + 3u;
    TFR(17) TFR(29) TFR(16) TFR(24)
    x0 += k1; x1 += ks2 + 4u;
    TFR(13) TFR(15) TFR(26) TFR(6)
    x0 += ks2; x1 += k0 + 5u;
#undef TFR
    o0 = x0; o1 = x1;
}
__device__ __forceinline__ unsigned tf_bits32(unsigned k0, unsigned k1, unsigned i){
    unsigned o0, o1;
    tf2x32(k0, k1, 0u, i, o0, o1);
    return o0 ^ o1;
}
__device__ __forceinline__ float gumbel_from_bits(unsigned b){
    const float TINY = 1.17549435e-38f;
    float f = __uint_as_float((b >> 9) | 0x3f800000u) - 1.0f;
    float u = fmaxf(TINY, f*(1.0f - TINY) + TINY);
    return -logf(-logf(u));
}

// ---- fused encoder ----
__global__ void enc_fused_kernel(const float* __restrict__ x, const float* __restrict__ pos,
                                 const int* __restrict__ ntype, const float* __restrict__ temb,
                                 const float* __restrict__ w1, const float* __restrict__ b1,
                                 const float* __restrict__ w2, const float* __restrict__ b2,
                                 float* __restrict__ out){
    __shared__ float w1s[15*HID];
    __shared__ float w2s[HID*HID];
    __shared__ float hid[4][HID];
    int tid = threadIdx.x;
    for (int i = tid; i < 15*HID; i += 256) w1s[i] = w1[i];
    for (int i = tid; i < HID*HID; i += 256) w2s[i] = w2[i];
    int r = tid >> 6, c = tid & 63;
    int n = blockIdx.x*4 + r;
    float nf[15];
    nf[0]=x[n*4+0]; nf[1]=x[n*4+1]; nf[2]=x[n*4+2]; nf[3]=x[n*4+3];
    nf[4]=pos[n*3+0]; nf[5]=pos[n*3+1]; nf[6]=pos[n*3+2];
    int t = ntype[n];
    #pragma unroll
    for (int d=0; d<8; d++) nf[7+d] = temb[t*8+d];
    __syncthreads();
    float acc = b1[c];
    #pragma unroll
    for (int d=0; d<15; d++) acc += nf[d]*w1s[d*HID+c];
    hid[r][c] = fmaxf(acc, 0.f);
    __syncthreads();
    float o = b2[c];
    #pragma unroll
    for (int k=0;k<HID;k++) o += hid[r][k]*w2s[k*HID+c];
    out[n*HID+c] = o;
}

// ---- init ----
__global__ void init_all_kernel(){
    int i = blockIdx.x*blockDim.x+threadIdx.x;
    if (i < NN*HID){ g_acc1[i]=0.f; g_acc2[i]=0.f; }
    if (i < NN*8) g_sums[i]=0.f;
    if (i < NN*HEADS){ g_denom1[i]=0.f; g_denom2[i]=0.f; }
    if (i < NN) g_cnt[i]=1;                 // +1 self-loop slot per dst
    if (i < KC*HID) g_feats[i]=0.f;
}

// ---- self-loop sums + CSR histogram ----
__global__ void loop_accum_kernel(const int* __restrict__ ei, const float* __restrict__ ea){
    int e = blockIdx.x*blockDim.x+threadIdx.x;
    if (e >= EE) return;
    int dst = ei[EE + e];
    atomicAdd(&g_cnt[dst], 1);
    float2 e01 = *(const float2*)(ea + e*6);
    float2 e23 = *(const float2*)(ea + e*6 + 2);
    float2 e45 = *(const float2*)(ea + e*6 + 4);
    float* p = &g_sums[dst*8];
    RED4(p,   e01.x, e01.y, e23.x, e23.y);
    RED4(p+4, e45.x, e45.y, 1.0f, 0.0f);
}

// ---- CSR scan (1 block) ----
__global__ void __launch_bounds__(1024) csr_scan_kernel(){
    __shared__ int sm[NN];
    int tid = threadIdx.x;
    sm[tid]      = g_cnt[tid];
    sm[tid+1024] = g_cnt[tid+1024];
    __syncthreads();
    for (int off=1; off<NN; off<<=1){
        int a = (tid        >= off) ? sm[tid-off]      : 0;
        int b = (tid+1024   >= off) ? sm[tid+1024-off] : 0;
        __syncthreads();
        sm[tid]      += a;
        sm[tid+1024] += b;
        __syncthreads();
    }
    if (tid == 0) g_rowptr[0] = 0;
    g_rowptr[tid+1]    = sm[tid];
    g_rowptr[tid+1025] = sm[tid+1024];
    g_cnt[tid] = 0;
    g_cnt[tid+1024] = 0;
}

// ---- CSR fill (edges + self-loops) ----
__global__ void csr_fill_kernel(const int* __restrict__ ei){
    int i = blockIdx.x*blockDim.x+threadIdx.x;
    if (i >= NEP) return;
    int dst = (i < EE) ? ei[EE+i] : (i - EE);
    int r = atomicAdd(&g_cnt[dst], 1);
    int slot = g_rowptr[dst] + r;
    g_eids[slot] = i;       // i>=EE marks self-loop
    g_edst[slot] = dst;
}

// ---- plain dual GEMM ----
__global__ void gemm64_dual_kernel(const float* __restrict__ in,
                                   const float* __restrict__ wA, const float* __restrict__ bA,
                                   const float* __restrict__ wB, const float* __restrict__ bB,
                                   float* __restrict__ oA, float* __restrict__ oB){
    __shared__ float wsA[HID*HID];
    __shared__ float wsB[HID*HID];
    __shared__ float ins[4][HID];
    int tid = threadIdx.x;
    for (int i = tid; i < HID*HID; i += 256){ wsA[i] = wA[i]; wsB[i] = wB[i]; }
    int r = tid >> 6, c = tid & 63;
    int row = blockIdx.x*4 + r;
    ins[r][c] = in[row*HID + c];
    __syncthreads();
    float aA = bA ? bA[c] : 0.f;
    float aB = bB ? bB[c] : 0.f;
    #pragma unroll
    for (int k=0;k<HID;k++){
        float v = ins[r][k];
        aA += v*wsA[k*HID+c];
        aB += v*wsB[k*HID+c];
    }
    oA[row*HID+c] = aA;
    oB[row*HID+c] = aB;
}

// ---- dual GEMM with fused GAT normalize epilogue on input ----
__global__ void gemm64_dual_gat_kernel(const float* __restrict__ acc, const float* __restrict__ denom,
                                       const float* __restrict__ gbias, int act,
                                       const float* __restrict__ wA, const float* __restrict__ bA,
                                       const float* __restrict__ wB, const float* __restrict__ bB,
                                       float* __restrict__ oA, float* __restrict__ oB,
                                       float* __restrict__ hstore){
    __shared__ float wsA[HID*HID];
    __shared__ float wsB[HID*HID];
    __shared__ float ins[4][HID];
    int tid = threadIdx.x;
    for (int i = tid; i < HID*HID; i += 256){ wsA[i] = wA[i]; wsB[i] = wB[i]; }
    int r = tid >> 6, c = tid & 63;
    int row = blockIdx.x*4 + r;
    {
        float v = acc[row*HID+c] / denom[row*HEADS + (c>>4)] + gbias[c];
        if (act) v = fmaxf(v, 0.f);
        ins[r][c] = v;
        if (hstore) hstore[row*HID+c] = v;
    }
    __syncthreads();
    float aA = bA ? bA[c] : 0.f;
    float aB = bB ? bB[c] : 0.f;
    #pragma unroll
    for (int k=0;k<HID;k++){
        float v = ins[r][k];
        aA += v*wsA[k*HID+c];
        aB += v*wsB[k*HID+c];
    }
    oA[row*HID+c] = aA;
    oB[row*HID+c] = aB;
}

// ---- GAT edge pass over CSR with warp-segmented reduction ----
// warp = 32 consecutive CSR items, one head. dsts non-decreasing in warp.
// NEP/32 = 2112 warps per head, x4 heads = 8448 warps = 1056 blocks x 8 warps.
__global__ void __launch_bounds__(256) gat_pass12_csr_kernel(
        const int* __restrict__ ei, const float* __restrict__ ea,
        const float* __restrict__ we, const float* __restrict__ att,
        const float* __restrict__ xl, const float* __restrict__ xr,
        float* __restrict__ acc, float* __restrict__ denom){
    __shared__ float wes[6*HID];
    __shared__ float atts[HID];
    for (int i=threadIdx.x;i<6*HID;i+=256) wes[i]=we[i];
    if (threadIdx.x < HID) atts[threadIdx.x]=att[threadIdx.x];
    __syncthreads();
    int gw = blockIdx.x*8 + (threadIdx.x>>5);
    int lane = threadIdx.x & 31;
    int h = gw & 3;
    int idx = (gw>>2)*32 + lane;       // < NEP always (2112*32 == NEP)
    int base = h*HD;

    int eid = g_eids[idx];
    int dst = g_edst[idx];
    int src;
    float eav[6];
    if (eid < EE){
        src = ei[eid];
        float2 a01 = *(const float2*)(ea + eid*6);
        float2 a23 = *(const float2*)(ea + eid*6 + 2);
        float2 a45 = *(const float2*)(ea + eid*6 + 4);
        eav[0]=a01.x; eav[1]=a01.y; eav[2]=a23.x; eav[3]=a23.y; eav[4]=a45.x; eav[5]=a45.y;
    } else {
        src = dst;
        float cn = fmaxf(g_sums[dst*8+6], 1.f);
        #pragma unroll
        for (int d=0; d<6; d++) eav[d] = g_sums[dst*8+d] / cn;
    }
    const float4* xl4 = (const float4*)(xl + src*HID + base);
    const float4* xr4 = (const float4*)(xr + dst*HID + base);
    float xlv[16], lv[16];
    #pragma unroll
    for (int q=0;q<4;q++){
        float4 L = xl4[q], R = xr4[q];
        xlv[q*4+0]=L.x; xlv[q*4+1]=L.y; xlv[q*4+2]=L.z; xlv[q*4+3]=L.w;
        lv[q*4+0]=L.x+R.x; lv[q*4+1]=L.y+R.y; lv[q*4+2]=L.z+R.z; lv[q*4+3]=L.w+R.w;
    }
    float lo = 0.f;
    #pragma unroll
    for (int k=0;k<HD;k++){
        float v = lv[k];
        #pragma unroll
        for (int d=0;d<6;d++) v += eav[d]*wes[d*HID+base+k];
        v = (v > 0.f) ? v : 0.2f*v;
        lo += v*atts[base+k];
    }
    float ex = expf(lo);
    float m[16];
    #pragma unroll
    for (int k=0;k<HD;k++) m[k] = xlv[k]*ex;

    // segmented suffix reduction over contiguous same-dst runs
    #pragma unroll
    for (int off=1; off<32; off<<=1){
        int d2 = __shfl_down_sync(0xffffffffu, dst, off);
        float s2 = __shfl_down_sync(0xffffffffu, ex, off);
        float m2[16];
        #pragma unroll
        for (int k=0;k<HD;k++) m2[k] = __shfl_down_sync(0xffffffffu, m[k], off);
        bool take = (lane + off < 32) && (d2 == dst);
        if (take){
            ex += s2;
            #pragma unroll
            for (int k=0;k<HD;k++) m[k] += m2[k];
        }
    }
    int dprev = __shfl_up_sync(0xffffffffu, dst, 1);
    bool leader = (lane == 0) || (dprev != dst);
    if (leader){
        atomicAdd(&denom[dst*HEADS+h], ex);
        float* accp = acc + dst*HID + base;
        RED4(accp,    m[0],  m[1],  m[2],  m[3]);
        RED4(accp+4,  m[4],  m[5],  m[6],  m[7]);
        RED4(accp+8,  m[8],  m[9],  m[10], m[11]);
        RED4(accp+12, m[12], m[13], m[14], m[15]);
    }
}

// ---- association matrix ----
__global__ void __launch_bounds__(256) assoc_kernel(
        const float* __restrict__ si, const float* __restrict__ sj,
        const float* __restrict__ w2, const float* __restrict__ b2,
        float* __restrict__ A){
    __shared__ __align__(16) float sis[64][68];
    __shared__ __align__(16) float sjs[64][68];
    __shared__ float w2h[64];
    int tid = threadIdx.x;
    int bi = blockIdx.y*64, bj = blockIdx.x*64;
    for (int i=tid;i<64*64;i+=256){
        int r = i >> 6, c = i & 63;
        sis[c][r] = si[(bi+r)*HID + c];
        sjs[c][r] = sj[(bj+r)*HID + c];
    }
    if (tid < 64) w2h[tid] = 0.5f*w2[tid];
    __syncthreads();
    int tx = tid & 31, ty = tid >> 5;
    int ib = 8*ty, jb = 2*tx;
    const ull MASK = 0x7FFFFFFF7FFFFFFFULL;
    ull acc[4][2];
    #pragma unroll
    for (int p=0;p<4;p++){ acc[p][0]=0ULL; acc[p][1]=0ULL; }
    #pragma unroll 8
    for (int c=0;c<64;c++){
        double2 A01 = *(const double2*)&sis[c][ib];
        double2 A23 = *(const double2*)&sis[c][ib+4];
        ull ap[4] = { __double_as_longlong(A01.x), __double_as_longlong(A01.y),
                      __double_as_longlong(A23.x), __double_as_longlong(A23.y) };
        ull pv0 = px2_dup(sjs[c][jb]);
        ull pv1 = px2_dup(sjs[c][jb+1]);
        ull pw  = px2_dup(w2h[c]);
        #pragma unroll
        for (int p=0;p<4;p++){
            ull t0 = px2_add(ap[p], pv0);
            t0 = px2_add(t0, t0 & MASK);
            acc[p][0] = px2_fma(t0, pw, acc[p][0]);
            ull t1 = px2_add(ap[p], pv1);
            t1 = px2_add(t1, t1 & MASK);
            acc[p][1] = px2_fma(t1, pw, acc[p][1]);
        }
    }
    float b2v = b2[0];
    #pragma unroll
    for (int p=0;p<4;p++){
        float o00 = __uint_as_float((unsigned)(acc[p][0]));
        float o01 = __uint_as_float((unsigned)(acc[p][0]>>32));
        float o10 = __uint_as_float((unsigned)(acc[p][1]));
        float o11 = __uint_as_float((unsigned)(acc[p][1]>>32));
        int i0 = bi + ib + 2*p;
        size_t r0o = (size_t)i0*NN + bj + jb;
        size_t r1o = (size_t)(i0+1)*NN + bj + jb;
        A[r0o]   = 1.f/(1.f+expf(-(o00+b2v)));
        A[r0o+1] = 1.f/(1.f+expf(-(o10+b2v)));
        A[r1o]   = 1.f/(1.f+expf(-(o01+b2v)));
        A[r1o+1] = 1.f/(1.f+expf(-(o11+b2v)));
    }
}

// ---- soft clustering (VERBATIM; do not touch) ----
__global__ void __launch_bounds__(1024) cluster_kernel(const float* __restrict__ A){
    __shared__ float s_mind[NN];
    __shared__ float s_wv[32];
    __shared__ int   s_wi[32];
    __shared__ unsigned s_k0[KC-1], s_k1[KC-1];
    __shared__ int s_nxt;
    __shared__ float s_inv;
    __shared__ unsigned s_kq0, s_kq1;
    int tid = threadIdx.x;
    int lane = tid & 31, wid = tid >> 5;

    if (tid == 0){
        unsigned kf0,kf1, kq0,kq1;
        tf2x32(0u,42u, 0u,0u, kf0,kf1);
        tf2x32(0u,42u, 0u,1u, kq0,kq1);
        s_kq0 = kq0; s_kq1 = kq1;
        unsigned s2_0, s2_1;
        tf2x32(kf0, kf1, 0u, 1u, s2_0, s2_1);
        unsigned lower = tf_bits32(s2_0, s2_1, 0u);
        int first = (int)(lower % (unsigned)NN);
        s_nxt = first;
        g_idx[0] = first;
    }
    __syncthreads();
    if (tid < KC-1){
        unsigned o0,o1;
        tf2x32(s_kq0, s_kq1, 0u, (unsigned)tid, o0, o1);
        s_k0[tid]=o0; s_k1[tid]=o1;
    }
    __syncthreads();
    {
        int first = s_nxt;
        s_mind[tid]      = 1.0f - A[(size_t)first*NN + tid];
        s_mind[tid+1024] = 1.0f - A[(size_t)first*NN + tid + 1024];
    }
    __syncthreads();

    for (int step=0; step<KC-1; step++){
        float s = s_mind[tid] + s_mind[tid+1024];
        #pragma unroll
        for (int o=16;o>0;o>>=1) s += __shfl_down_sync(0xffffffffu, s, o);
        if (lane==0) s_wv[wid]=s;
        __syncthreads();
        if (wid==0){
            float t = s_wv[lane];
            #pragma unroll
            for (int o=16;o>0;o>>=1) t += __shfl_down_sync(0xffffffffu, t, o);
            if (lane==0) s_inv = 1.0f/(t + 1e-8f);
        }
        __syncthreads();
        float inv = s_inv;
        unsigned b0 = tf_bits32(s_k0[step], s_k1[step], (unsigned)tid);
        unsigned b1 = tf_bits32(s_k0[step], s_k1[step], (unsigned)(tid+1024));
        float sc0 = logf(fmaxf(s_mind[tid]*inv,      1e-30f)) + gumbel_from_bits(b0);
        float sc1 = logf(fmaxf(s_mind[tid+1024]*inv, 1e-30f)) + gumbel_from_bits(b1);
        float bv; int bi;
        if (sc0 >= sc1){ bv = sc0; bi = tid; } else { bv = sc1; bi = tid + 1024; }
        #pragma unroll
        for (int o=16;o>0;o>>=1){
            float ov = __shfl_down_sync(0xffffffffu, bv, o);
            int   oi = __shfl_down_sync(0xffffffffu, bi, o);
            if (ov > bv || (ov == bv && oi < bi)){ bv = ov; bi = oi; }
        }
        if (lane==0){ s_wv[wid]=bv; s_wi[wid]=bi; }
        __syncthreads();
        if (wid==0){
            float v = s_wv[lane]; int ix = s_wi[lane];
            #pragma unroll
            for (int o=16;o>0;o>>=1){
                float ov = __shfl_down_sync(0xffffffffu, v, o);
                int   oi = __shfl_down_sync(0xffffffffu, ix, o);
                if (ov > v || (ov == v && oi < ix)){ v = ov; ix = oi; }
            }
            if (lane==0){ s_nxt = ix; g_idx[step+1] = ix; }
        }
        __syncthreads();
        int nxt = s_nxt;
        s_mind[tid]      = fminf(s_mind[tid],      1.0f - A[(size_t)nxt*NN + tid]);
        s_mind[tid+1024] = fminf(s_mind[tid+1024], 1.0f - A[(size_t)nxt*NN + tid + 1024]);
        __syncthreads();
    }
}

// ---- assign ----
__global__ void assign_kernel(const float* __restrict__ A, float* __restrict__ assign){
    __shared__ int idxs[KC];
    if (threadIdx.x < KC) idxs[threadIdx.x] = g_idx[threadIdx.x];
    __syncthreads();
    int n = blockIdx.x*blockDim.x + threadIdx.x;
    if (n >= NN) return;
    float v[KC];
    float mx = -3.4e38f;
    #pragma unroll
    for (int k=0;k<KC;k++){
        v[k] = A[(size_t)n*NN + idxs[k]] * 10.0f;
        mx = fmaxf(mx, v[k]);
    }
    float sum = 0.f;
    #pragma unroll
    for (int k=0;k<KC;k++){ v[k] = expf(v[k]-mx); sum += v[k]; }
    float invs = 1.0f/sum;
    #pragma unroll
    for (int k=0;k<KC;k++) assign[n*KC+k] = v[k]*invs;
}

// ---- feats: grid (KC, 8), per-block partial + atomicAdd ----
__global__ void feats_kernel(const float* __restrict__ assign, const float* __restrict__ h){
    int k = blockIdx.x;
    int n0 = blockIdx.y * 256;
    int tid = threadIdx.x;
    int c = tid & 63, g = tid >> 6;
    __shared__ float a_s[256];
    __shared__ float part[4][HID];
    a_s[tid] = assign[(n0+tid)*KC + k];
    __syncthreads();
    float acc = 0.f;
    for (int nn=g; nn<256; nn+=4)
        acc += a_s[nn]*h[(size_t)(n0+nn)*HID + c];
    part[g][c] = acc;
    __syncthreads();
    if (g == 0)
        atomicAdd(&g_feats[k*HID+c], part[0][c]+part[1][c]+part[2][c]+part[3][c]);
}

// ---- preds ----
__global__ void preds_kernel(const float* __restrict__ w1, const float* __restrict__ b1,
                             const float* __restrict__ w2, const float* __restrict__ b2,
                             float* __restrict__ preds){
    __shared__ float hid[HID];
    int k = blockIdx.x, c = threadIdx.x;
    float acc = b1[c];
    #pragma unroll
    for (int d=0;d<HID;d++) acc += g_feats[k*HID+d]*w1[d*HID+c];
    hid[c] = fmaxf(acc, 0.f);
    __syncthreads();
    if (c < PRED_DIM){
        float p = b2[c];
        #pragma unroll
        for (int d=0;d<HID;d++) p += hid[d]*w2[d*PRED_DIM+c];
        preds[k*PRED_DIM+c] = p;
    }
}

extern "C" void kernel_launch(void* const* d_in, const int* in_sizes, int n_in,
                              void* d_out, int out_size) {
    const float* x        = (const float*)d_in[0];
    const float* pos      = (const float*)d_in[1];
    const int*   ntype    = (const int*)d_in[2];
    const int*   ei       = (const int*)d_in[3];
    const float* ea       = (const float*)d_in[4];
    const float* temb     = (const float*)d_in[5];
    const float* enc_w1   = (const float*)d_in[6];
    const float* enc_b1   = (const float*)d_in[7];
    const float* enc_w2   = (const float*)d_in[8];
    const float* enc_b2   = (const float*)d_in[9];
    const float* g1_wl  = (const float*)d_in[10];
    const float* g1_bl  = (const float*)d_in[11];
    const float* g1_wr  = (const float*)d_in[12];
    const float* g1_br  = (const float*)d_in[13];
    const float* g1_we  = (const float*)d_in[14];
    const float* g1_att = (const float*)d_in[15];
    const float* g1_bias= (const float*)d_in[16];
    const float* g2_wl  = (const float*)d_in[17];
    const float* g2_bl  = (const float*)d_in[18];
    const float* g2_wr  = (const float*)d_in[19];
    const float* g2_br  = (const float*)d_in[20];
    const float* g2_we  = (const float*)d_in[21];
    const float* g2_att = (const float*)d_in[22];
    const float* g2_bias= (const float*)d_in[23];
    const float* ah_w1  = (const float*)d_in[24];
    const float* ah_b1  = (const float*)d_in[25];
    const float* ah_w2  = (const float*)d_in[26];
    const float* ah_b2  = (const float*)d_in[27];
    const float* dec_w1 = (const float*)d_in[28];
    const float* dec_b1 = (const float*)d_in[29];
    const float* dec_w2 = (const float*)d_in[30];
    const float* dec_b2 = (const float*)d_in[31];

    float* out      = (float*)d_out;
    float* predsOut = out;
    float* Aout     = out + KC*PRED_DIM;
    float* assignO  = Aout + (size_t)NN*NN;

    float *h0, *h2, *bA, *bB, *acc1, *acc2, *den1, *den2;
    cudaGetSymbolAddress((void**)&h0,   g_h0);
    cudaGetSymbolAddress((void**)&h2,   g_h2);
    cudaGetSymbolAddress((void**)&bA,   g_bufA);
    cudaGetSymbolAddress((void**)&bB,   g_bufB);
    cudaGetSymbolAddress((void**)&acc1, g_acc1);
    cudaGetSymbolAddress((void**)&acc2, g_acc2);
    cudaGetSymbolAddress((void**)&den1, g_denom1);
    cudaGetSymbolAddress((void**)&den2, g_denom2);

    const int PASS_BLOCKS = (NEP/32)*HEADS/8;   // 2112*4/8 = 1056

    init_all_kernel<<<(NN*HID+255)/256, 256>>>();
    enc_fused_kernel<<<NN/4, 256>>>(x, pos, ntype, temb, enc_w1, enc_b1, enc_w2, enc_b2, h0);

    loop_accum_kernel<<<EE/256, 256>>>(ei, ea);
    csr_scan_kernel<<<1, 1024>>>();
    csr_fill_kernel<<<(NEP+255)/256, 256>>>(ei);

    // GAT layer 1
    gemm64_dual_kernel<<<NN/4, 256>>>(h0, g1_wl, g1_bl, g1_wr, g1_br, bA, bB);
    gat_pass12_csr_kernel<<<PASS_BLOCKS, 256>>>(ei, ea, g1_we, g1_att, bA, bB, acc1, den1);

    // GAT layer 2 (layer-1 normalize fused into gemm input)
    gemm64_dual_gat_kernel<<<NN/4, 256>>>(acc1, den1, g1_bias, 1,
                                          g2_wl, g2_bl, g2_wr, g2_br, bA, bB, nullptr);
    gat_pass12_csr_kernel<<<PASS_BLOCKS, 256>>>(ei, ea, g2_we, g2_att, bA, bB, acc2, den2);

    // association matrix (layer-2 normalize fused; h2 materialized)
    gemm64_dual_gat_kernel<<<NN/4, 256>>>(acc2, den2, g2_bias, 0,
                                          ah_w1, ah_b1, ah_w1 + HID*HID, nullptr, bA, bB, h2);
    assoc_kernel<<<dim3(NN/64, NN/64), 256>>>(bA, bB, ah_w2, ah_b2, Aout);

    // clustering + epilogue
    cluster_kernel<<<1, 1024>>>(Aout);
    assign_kernel<<<NN/256, 256>>>(Aout, assignO);
    feats_kernel<<<dim3(KC, 8), 256>>>(assignO, h2);
    preds_kernel<<<KC, HID>>>(dec_w1, dec_b1, dec_w2, dec_b2, predsOut);
}